// round 12
// baseline (speedup 1.0000x reference)
#include <cuda_runtime.h>
#include <cuda_bf16.h>
#include <cstdint>

#define NMAX 50000
#define EMAX 600000
#define H 128

// ---------------- scratch (device globals; no allocation allowed) -------------
__device__ float g_h[NMAX * H];
__device__ float g_tmp[NMAX * H];
__device__ float g_agg[NMAX * H];
__device__ int   g_rptr[NMAX + 1];
__device__ int   g_cnt[NMAX];
__device__ int   g_part[256];
__device__ int2  g_csr[EMAX];
__device__ float g_sum[H];
__device__ float g_sumsq[H];
__device__ float g_scale[H];
__device__ float g_shift[H];
// pre-split weights: hi/lo bf16 planes in final swizzled layout
__device__ __align__(16) char g_wbuf[622592];

// ---------------- helpers -----------------------------------------------------
__device__ __forceinline__ uint32_t smem_to_u32(const void* p) {
    uint32_t a;
    asm("{ .reg .u64 t; cvta.to.shared.u64 t, %1; cvt.u32.u64 %0, t; }" : "=r"(a) : "l"(p));
    return a;
}

#define LDSM4(r0, r1, r2, r3, addr) \
    asm volatile("ldmatrix.sync.aligned.m8n8.x4.shared.b16 {%0,%1,%2,%3}, [%4];" \
        : "=r"(r0), "=r"(r1), "=r"(r2), "=r"(r3) : "r"(addr))

#define MMA16816(d, a, b0v, b1v) \
    asm volatile("mma.sync.aligned.m16n8k16.row.col.f32.bf16.bf16.f32 " \
        "{%0,%1,%2,%3},{%4,%5,%6,%7},{%8,%9},{%0,%1,%2,%3};" \
        : "+f"((d)[0]), "+f"((d)[1]), "+f"((d)[2]), "+f"((d)[3]) \
        : "r"((a)[0]), "r"((a)[1]), "r"((a)[2]), "r"((a)[3]), "r"(b0v), "r"(b1v))

__device__ __forceinline__ void cvt_pair(float a, float b, uint32_t& hi, uint32_t& lo) {
    __nv_bfloat16 ha = __float2bfloat16(a), hb = __float2bfloat16(b);
    __nv_bfloat16 la = __float2bfloat16(a - __bfloat162float(ha));
    __nv_bfloat16 lb = __float2bfloat16(b - __bfloat162float(hb));
    __nv_bfloat162 hp; hp.x = ha; hp.y = hb;
    __nv_bfloat162 lp; lp.x = la; lp.y = lb;
    hi = *reinterpret_cast<uint32_t*>(&hp);
    lo = *reinterpret_cast<uint32_t*>(&lp);
}

// 3-pass split MMA (order hh, lh, hl — B-hi fragment reused across hh/lh).
// 10 LDSM4 + 24 MMA per ks vs 12 LDSM4 before. acc order change is fp32-benign.
__device__ __forceinline__ void mma3pass(uint32_t sb, uint32_t aH, uint32_t aL,
                                         uint32_t bH, uint32_t bL,
                                         int rmb, int n0w, int lid,
                                         float acc[2][4][4])
{
    #pragma unroll
    for (int ks = 0; ks < 4; ks++) {
        int crow = ks * 2 + (lid >> 4);
        uint32_t af[2][4], bf[2][4];
        int r0 = rmb + (lid & 15), r1 = rmb + 16 + (lid & 15);
        int n0 = n0w + (lid & 15), n1 = n0w + 16 + (lid & 15);
        uint32_t adH0 = sb + aH + r0 * 128 + ((crow ^ (r0 & 7)) << 4);
        uint32_t adH1 = sb + aH + r1 * 128 + ((crow ^ (r1 & 7)) << 4);
        uint32_t adL0 = sb + aL + r0 * 128 + ((crow ^ (r0 & 7)) << 4);
        uint32_t adL1 = sb + aL + r1 * 128 + ((crow ^ (r1 & 7)) << 4);
        uint32_t bdH0 = sb + bH + n0 * 128 + ((crow ^ (n0 & 7)) << 4);
        uint32_t bdH1 = sb + bH + n1 * 128 + ((crow ^ (n1 & 7)) << 4);
        uint32_t bdL0 = sb + bL + n0 * 128 + ((crow ^ (n0 & 7)) << 4);
        uint32_t bdL1 = sb + bL + n1 * 128 + ((crow ^ (n1 & 7)) << 4);

        #define DO_MMA8() \
            _Pragma("unroll") \
            for (int mi = 0; mi < 2; mi++) \
                _Pragma("unroll") \
                for (int ni = 0; ni < 4; ni++) { \
                    uint32_t b0v = bf[ni >> 1][ni & 1]; \
                    uint32_t b1v = bf[ni >> 1][(ni & 1) + 2]; \
                    MMA16816(acc[mi][ni], af[mi], b0v, b1v); \
                }

        // pass hh
        LDSM4(bf[0][0], bf[0][1], bf[0][2], bf[0][3], bdH0);
        LDSM4(bf[1][0], bf[1][1], bf[1][2], bf[1][3], bdH1);
        LDSM4(af[0][0], af[0][1], af[0][2], af[0][3], adH0);
        LDSM4(af[1][0], af[1][1], af[1][2], af[1][3], adH1);
        DO_MMA8()
        // pass lh (reuse bf = B-hi)
        LDSM4(af[0][0], af[0][1], af[0][2], af[0][3], adL0);
        LDSM4(af[1][0], af[1][1], af[1][2], af[1][3], adL1);
        DO_MMA8()
        // pass hl
        LDSM4(bf[0][0], bf[0][1], bf[0][2], bf[0][3], bdL0);
        LDSM4(bf[1][0], bf[1][1], bf[1][2], bf[1][3], bdL1);
        LDSM4(af[0][0], af[0][1], af[0][2], af[0][3], adH0);
        LDSM4(af[1][0], af[1][1], af[1][2], af[1][3], adH1);
        DO_MMA8()
        #undef DO_MMA8
    }
}

// ---------------- weight pre-split kernel -------------------------------------
__global__ __launch_bounds__(256) void wprep_k(
    const float* __restrict__ enc_w1, const float* __restrict__ enc_w2,
    const float* __restrict__ mlp_w1, const float* __restrict__ mlp_w2)
{
    int g = blockIdx.x * 256 + threadIdx.x;
    const float* W;
    uint32_t bufoff;
    int local;
    if (g < 1024)       { W = enc_w1; bufoff = 0;     local = g; }
    else if (g < 3072)  { W = enc_w2; bufoff = 32768; local = g - 1024; }
    else if (g < 11264) {
        int l = (g - 3072) >> 11;
        W = mlp_w1 + l * 16384; bufoff = 98304 + l * 65536; local = (g - 3072) & 2047;
    } else if (g < 19456) {
        int l = (g - 11264) >> 11;
        W = mlp_w2 + l * 16384; bufoff = 360448 + l * 65536; local = (g - 11264) & 2047;
    } else return;

    int nn = local & 127;
    int t  = local >> 7;
    int ci = t >> 3, cc = t & 7;
    float v[8];
    #pragma unroll
    for (int j = 0; j < 8; j++)
        v[j] = W[(size_t)(ci * 64 + cc * 8 + j) * 128 + nn];
    uint4 hi, lo;
    cvt_pair(v[0], v[1], hi.x, lo.x);
    cvt_pair(v[2], v[3], hi.y, lo.y);
    cvt_pair(v[4], v[5], hi.z, lo.z);
    cvt_pair(v[6], v[7], hi.w, lo.w);
    uint32_t off = nn * 128 + ((cc ^ (nn & 7)) << 4);
    char* base = g_wbuf + bufoff + ci * 32768;
    *(uint4*)(base + off) = hi;
    *(uint4*)(base + 16384 + off) = lo;
}

// ---------------- block-scan helper (256 threads, inclusive) ------------------
__device__ __forceinline__ int block_scan_256(int v, int tid, int* wsum) {
    int lane = tid & 31, wid = tid >> 5;
    #pragma unroll
    for (int o = 1; o < 32; o <<= 1) {
        int t = __shfl_up_sync(0xffffffffu, v, o);
        if (lane >= o) v += t;
    }
    if (lane == 31) wsum[wid] = v;
    __syncthreads();
    if (wid == 0) {
        int s = (lane < 8) ? wsum[lane] : 0;
        #pragma unroll
        for (int o = 1; o < 8; o <<= 1) {
            int t = __shfl_up_sync(0xffffffffu, s, o);
            if (lane >= o) s += t;
        }
        if (lane < 8) wsum[lane] = s;
    }
    __syncthreads();
    if (wid > 0) v += wsum[wid - 1];
    return v;
}

// ---------------- CSR build ---------------------------------------------------
__global__ void zero_cnt_k(int n) {
    int i = blockIdx.x * blockDim.x + threadIdx.x;
    if (i < n) g_cnt[i] = 0;
}
__global__ void hist_k(const int* __restrict__ dst, int e) {
    int i = blockIdx.x * blockDim.x + threadIdx.x;
    if (i < e) atomicAdd(&g_cnt[dst[i]], 1);
}
__global__ __launch_bounds__(256) void scan1_k(int n) {
    __shared__ int wsum[32];
    int tid = threadIdx.x, lane = tid & 31, wid = tid >> 5;
    int i = blockIdx.x * 256 + tid;
    int v = (i < n) ? g_cnt[i] : 0;
    #pragma unroll
    for (int o = 16; o > 0; o >>= 1) v += __shfl_down_sync(0xffffffffu, v, o);
    if (lane == 0) wsum[wid] = v;
    __syncthreads();
    if (wid == 0) {
        int s = (lane < 8) ? wsum[lane] : 0;
        #pragma unroll
        for (int o = 4; o > 0; o >>= 1) s += __shfl_down_sync(0xffffffffu, s, o);
        if (lane == 0) g_part[blockIdx.x] = s;
    }
}
__global__ __launch_bounds__(256) void scan2_k(int nb) {
    __shared__ int wsum[32];
    int tid = threadIdx.x;
    int v = (tid < nb) ? g_part[tid] : 0;
    int inc = block_scan_256(v, tid, wsum);
    if (tid < nb) g_part[tid] = inc - v;
}
// scan3 also re-zeros g_cnt for fill_k (saves a separate zero pass)
__global__ __launch_bounds__(256) void scan3_k(int n) {
    __shared__ int wsum[32];
    int tid = threadIdx.x;
    int i = blockIdx.x * 256 + tid;
    int v = (i < n) ? g_cnt[i] : 0;
    int inc = block_scan_256(v, tid, wsum);
    if (i < n) {
        g_rptr[i + 1] = inc + g_part[blockIdx.x];
        g_cnt[i] = 0;
    }
    if (i == 0) g_rptr[0] = 0;
}
__global__ void fill_k(const int* __restrict__ src, const int* __restrict__ dst, int e) {
    int i = blockIdx.x * blockDim.x + threadIdx.x;
    if (i < e) {
        int d = dst[i];
        int p = g_rptr[d] + atomicAdd(&g_cnt[d], 1);
        g_csr[p] = make_int2(src[i], i);
    }
}

// ---------------- fused 2-layer MLP (512 thr, 32x32 warp tiles, opt stats) ----
template<int KA, bool NORM_A, bool ADD2, bool STATS>
__global__ __launch_bounds__(512) void fused_mlp_k(
    const float* __restrict__ Z, const float* __restrict__ AG,
    const uint4* __restrict__ w1s, const float* __restrict__ b1,
    const uint4* __restrict__ w2s, const float* __restrict__ b2,
    float* __restrict__ C, int M)
{
    extern __shared__ __align__(128) char smem[];
    __shared__ float ssum[128];
    __shared__ float ssq[128];
    uint32_t sb = smem_to_u32(smem);
    const uint32_t AH = 0, AL = 16384, BH = 32768;
    const uint32_t C1H = 0, C1L = 32768, B2H = 65536;

    int tid = threadIdx.x, lid = tid & 31, wid = tid >> 5;
    int m0 = blockIdx.x * 128;
    int rmb = (wid & 3) * 32;
    int n0w = (wid >> 2) * 32;
    int qr = lid >> 2, qc = lid & 3;

    if (STATS && tid < 128) { ssum[tid] = 0.f; ssq[tid] = 0.f; }

    float acc[2][4][4];
    #pragma unroll
    for (int mi = 0; mi < 2; mi++)
        #pragma unroll
        for (int ni = 0; ni < 4; ni++)
            #pragma unroll
            for (int j = 0; j < 4; j++) acc[mi][ni][j] = 0.f;

    // ================= GEMM 1 =================
    for (int kc = 0; kc < KA; kc += 64) {
        if (kc) __syncthreads();
        #pragma unroll
        for (int i = 0; i < 2; i++) {
            int cid = tid + i * 512;
            int r = cid >> 3, c = cid & 7;
            int gr = m0 + r;
            int col0 = kc + c * 8;
            float v[8];
            if (gr < M) {
                const float4* p = (const float4*)(Z + (size_t)gr * KA + col0);
                float4 v0 = p[0], v1 = p[1];
                v[0] = v0.x; v[1] = v0.y; v[2] = v0.z; v[3] = v0.w;
                v[4] = v1.x; v[5] = v1.y; v[6] = v1.z; v[7] = v1.w;
                if (NORM_A) {
                    float4 s0 = ((const float4*)g_scale)[col0 >> 2];
                    float4 s1 = ((const float4*)g_scale)[(col0 >> 2) + 1];
                    float4 t0 = ((const float4*)g_shift)[col0 >> 2];
                    float4 t1 = ((const float4*)g_shift)[(col0 >> 2) + 1];
                    v[0] = fmaxf(fmaf(v[0], s0.x, t0.x), 0.f);
                    v[1] = fmaxf(fmaf(v[1], s0.y, t0.y), 0.f);
                    v[2] = fmaxf(fmaf(v[2], s0.z, t0.z), 0.f);
                    v[3] = fmaxf(fmaf(v[3], s0.w, t0.w), 0.f);
                    v[4] = fmaxf(fmaf(v[4], s1.x, t1.x), 0.f);
                    v[5] = fmaxf(fmaf(v[5], s1.y, t1.y), 0.f);
                    v[6] = fmaxf(fmaf(v[6], s1.z, t1.z), 0.f);
                    v[7] = fmaxf(fmaf(v[7], s1.w, t1.w), 0.f);
                }
                if (ADD2) {
                    const float4* q = (const float4*)(AG + (size_t)gr * 128 + col0);
                    float4 w0 = q[0], w1 = q[1];
                    v[0] += w0.x; v[1] += w0.y; v[2] += w0.z; v[3] += w0.w;
                    v[4] += w1.x; v[5] += w1.y; v[6] += w1.z; v[7] += w1.w;
                }
            } else {
                #pragma unroll
                for (int j = 0; j < 8; j++) v[j] = 0.f;
            }
            uint4 hi, lo;
            cvt_pair(v[0], v[1], hi.x, lo.x);
            cvt_pair(v[2], v[3], hi.y, lo.y);
            cvt_pair(v[4], v[5], hi.z, lo.z);
            cvt_pair(v[6], v[7], hi.w, lo.w);
            uint32_t off = r * 128 + ((c ^ (r & 7)) << 4);
            *(uint4*)(smem + AH + off) = hi;
            *(uint4*)(smem + AL + off) = lo;
        }
        {
            const uint4* wp = w1s + (kc >> 6) * 2048;
            #pragma unroll
            for (int i = 0; i < 4; i++) {
                int idx = tid + i * 512;
                ((uint4*)(smem + BH))[idx] = wp[idx];
            }
        }
        __syncthreads();
        mma3pass(sb, AH, AL, BH, BH + 16384, rmb, n0w, lid, acc);
    }
    __syncthreads();

    // ================= C1 = relu(acc + b1) -> smem bf16 split =================
    #pragma unroll
    for (int ni = 0; ni < 4; ni++) {
        int col = n0w + ni * 8 + qc * 2;
        float bb0 = __ldg(b1 + col), bb1 = __ldg(b1 + col + 1);
        uint32_t plane = (uint32_t)(col >> 6) * 16384u;
        int cl = col & 63;
        int cc = cl >> 3;
        uint32_t cb = (uint32_t)((cl & 7) * 2);
        #pragma unroll
        for (int mi = 0; mi < 2; mi++) {
            int r0 = rmb + mi * 16 + qr;
            int r1 = r0 + 8;
            float o00 = fmaxf(acc[mi][ni][0] + bb0, 0.f);
            float o01 = fmaxf(acc[mi][ni][1] + bb1, 0.f);
            float o10 = fmaxf(acc[mi][ni][2] + bb0, 0.f);
            float o11 = fmaxf(acc[mi][ni][3] + bb1, 0.f);
            uint32_t h0, l0, h1, l1;
            cvt_pair(o00, o01, h0, l0);
            cvt_pair(o10, o11, h1, l1);
            uint32_t off0 = plane + r0 * 128 + ((cc ^ (r0 & 7)) << 4) + cb;
            uint32_t off1 = plane + r1 * 128 + ((cc ^ (r1 & 7)) << 4) + cb;
            *(uint32_t*)(smem + C1H + off0) = h0;
            *(uint32_t*)(smem + C1L + off0) = l0;
            *(uint32_t*)(smem + C1H + off1) = h1;
            *(uint32_t*)(smem + C1L + off1) = l1;
        }
    }
    #pragma unroll
    for (int mi = 0; mi < 2; mi++)
        #pragma unroll
        for (int ni = 0; ni < 4; ni++)
            #pragma unroll
            for (int j = 0; j < 4; j++) acc[mi][ni][j] = 0.f;

    // ================= GEMM 2 (K = 128, A = C1 in smem) =================
    for (int kc = 0; kc < 128; kc += 64) {
        if (kc) __syncthreads();
        {
            const uint4* wp = w2s + (kc >> 6) * 2048;
            #pragma unroll
            for (int i = 0; i < 4; i++) {
                int idx = tid + i * 512;
                ((uint4*)(smem + B2H))[idx] = wp[idx];
            }
        }
        __syncthreads();
        uint32_t plane = (uint32_t)(kc >> 6) * 16384u;
        mma3pass(sb, C1H + plane, C1L + plane, B2H, B2H + 16384, rmb, n0w, lid, acc);
    }

    // ================= epilogue: z = acc + b2 (+stats) =================
    #pragma unroll
    for (int ni = 0; ni < 4; ni++) {
        int col = n0w + ni * 8 + qc * 2;
        float b0 = __ldg(b2 + col), b1v = __ldg(b2 + col + 1);
        float s0 = 0.f, q0 = 0.f, s1 = 0.f, q1 = 0.f;
        #pragma unroll
        for (int mi = 0; mi < 2; mi++) {
            int gr = m0 + rmb + mi * 16 + qr;
            float2 o0 = make_float2(acc[mi][ni][0] + b0, acc[mi][ni][1] + b1v);
            float2 o1 = make_float2(acc[mi][ni][2] + b0, acc[mi][ni][3] + b1v);
            if (gr < M) {
                *(float2*)(C + (size_t)gr * 128 + col) = o0;
                if (STATS) { s0 += o0.x; q0 += o0.x * o0.x; s1 += o0.y; q1 += o0.y * o0.y; }
            }
            if (gr + 8 < M) {
                *(float2*)(C + (size_t)(gr + 8) * 128 + col) = o1;
                if (STATS) { s0 += o1.x; q0 += o1.x * o1.x; s1 += o1.y; q1 += o1.y * o1.y; }
            }
        }
        if (STATS) {
            atomicAdd(&ssum[col], s0);     atomicAdd(&ssq[col], q0);
            atomicAdd(&ssum[col + 1], s1); atomicAdd(&ssq[col + 1], q1);
        }
    }
    if (STATS) {
        __syncthreads();
        if (tid < 128) {
            atomicAdd(&g_sum[tid], ssum[tid]);
            atomicAdd(&g_sumsq[tid], ssq[tid]);
        }
    }
}

// ---------------- GINE aggregate (CSR, warp per node, fused norm) -------------
template<bool NORM>
__global__ __launch_bounds__(256) void agg_k(
    const float* __restrict__ h, const float* __restrict__ We,
    const float* __restrict__ be, const float* __restrict__ ea,
    float* __restrict__ out, int n)
{
    int lane = threadIdx.x & 31;
    int node = blockIdx.x * 8 + (threadIdx.x >> 5);

    const float4* We4 = (const float4*)We;
    float4 w[8];
    #pragma unroll
    for (int k = 0; k < 8; k++) w[k] = We4[k * 32 + lane];
    float4 bev = ((const float4*)be)[lane];
    float4 sc, sh;
    if (NORM) {
        sc = ((const float4*)g_scale)[lane];
        sh = ((const float4*)g_shift)[lane];
    }

    if (node >= n) return;
    int s = g_rptr[node], e = g_rptr[node + 1];

    const float4* h4  = (const float4*)h;
    const float4* ea4 = (const float4*)ea;
    float4 acc = make_float4(0.f, 0.f, 0.f, 0.f);

    for (int i = s; i < e; i++) {
        int2 se = g_csr[i];
        float4 a0 = ea4[se.y * 2];
        float4 a1 = ea4[se.y * 2 + 1];
        float4 hv = h4[se.x * 32 + lane];
        if (NORM) {
            hv.x = fmaxf(fmaf(hv.x, sc.x, sh.x), 0.f);
            hv.y = fmaxf(fmaf(hv.y, sc.y, sh.y), 0.f);
            hv.z = fmaxf(fmaf(hv.z, sc.z, sh.z), 0.f);
            hv.w = fmaxf(fmaf(hv.w, sc.w, sh.w), 0.f);
        }
        float4 lin = bev;
        #define ACCW(comp, wi) \
            lin.x = fmaf(comp, w[wi].x, lin.x); lin.y = fmaf(comp, w[wi].y, lin.y); \
            lin.z = fmaf(comp, w[wi].z, lin.z); lin.w = fmaf(comp, w[wi].w, lin.w);
        ACCW(a0.x, 0) ACCW(a0.y, 1) ACCW(a0.z, 2) ACCW(a0.w, 3)
        ACCW(a1.x, 4) ACCW(a1.y, 5) ACCW(a1.z, 6) ACCW(a1.w, 7)
        #undef ACCW
        acc.x += fmaxf(hv.x + lin.x, 0.f);
        acc.y += fmaxf(hv.y + lin.y, 0.f);
        acc.z += fmaxf(hv.z + lin.z, 0.f);
        acc.w += fmaxf(hv.w + lin.w, 0.f);
    }
    ((float4*)out)[node * 32 + lane] = acc;
}

// ---------------- GraphNorm ---------------------------------------------------
__global__ void zero_stats_k() {
    int c = threadIdx.x;
    g_sum[c] = 0.f;
    g_sumsq[c] = 0.f;
}

__global__ void finalize_k(const float* __restrict__ nw, const float* __restrict__ nb,
                           const float* __restrict__ na, float inv_n)
{
    int c = threadIdx.x;
    float s = g_sum[c], q = g_sumsq[c];
    g_sum[c] = 0.f;
    g_sumsq[c] = 0.f;
    float mu  = s * inv_n;
    float ez2 = q * inv_n;
    float a = na[c];
    float var = ez2 - (2.f * a - a * a) * mu * mu;
    float inv = rsqrtf(var + 1e-5f);
    g_scale[c] = nw[c] * inv;
    g_shift[c] = nb[c] - nw[c] * inv * a * mu;
}

__global__ __launch_bounds__(256) void decode_k(
    const float* __restrict__ z, const float* __restrict__ dec_w,
    const float* __restrict__ dec_b, float* __restrict__ out, int n)
{
    int lane = threadIdx.x & 31;
    int node = blockIdx.x * 8 + (threadIdx.x >> 5);
    if (node >= n) return;
    float4 sc = ((const float4*)g_scale)[lane];
    float4 sh = ((const float4*)g_shift)[lane];
    float4 zv = ((const float4*)z)[node * 32 + lane];
    float4 hv;
    hv.x = fmaxf(fmaf(zv.x, sc.x, sh.x), 0.f);
    hv.y = fmaxf(fmaf(zv.y, sc.y, sh.y), 0.f);
    hv.z = fmaxf(fmaf(zv.z, sc.z, sh.z), 0.f);
    hv.w = fmaxf(fmaf(zv.w, sc.w, sh.w), 0.f);
    float4 dw = ((const float4*)dec_w)[lane];
    float p = hv.x * dw.x + hv.y * dw.y + hv.z * dw.z + hv.w * dw.w;
    #pragma unroll
    for (int o = 16; o > 0; o >>= 1) p += __shfl_down_sync(0xffffffffu, p, o);
    if (lane == 0) out[node] = p + dec_b[0];
}

// ---------------- launch ------------------------------------------------------
extern "C" void kernel_launch(void* const* d_in, const int* in_sizes, int n_in,
                              void* d_out, int out_size)
{
    const float* x      = (const float*)d_in[0];
    const int*   ei     = (const int*)d_in[1];
    const float* ea     = (const float*)d_in[2];
    const float* enc_w1 = (const float*)d_in[3];
    const float* enc_b1 = (const float*)d_in[4];
    const float* enc_w2 = (const float*)d_in[5];
    const float* enc_b2 = (const float*)d_in[6];
    const float* edge_w = (const float*)d_in[7];
    const float* edge_b = (const float*)d_in[8];
    const float* mlp_w1 = (const float*)d_in[9];
    const float* mlp_b1 = (const float*)d_in[10];
    const float* mlp_w2 = (const float*)d_in[11];
    const float* mlp_b2 = (const float*)d_in[12];
    const float* norm_w = (const float*)d_in[13];
    const float* norm_b = (const float*)d_in[14];
    const float* norm_a = (const float*)d_in[15];
    const float* dec_w  = (const float*)d_in[16];
    const float* dec_b  = (const float*)d_in[17];

    int n = in_sizes[0] / 64;
    int e = in_sizes[2] / 8;
    const int* src = ei;
    const int* dst = ei + e;

    float *g_h_p, *g_tmp_p, *g_agg_p;
    char* wbuf;
    cudaGetSymbolAddress((void**)&g_h_p, g_h);
    cudaGetSymbolAddress((void**)&g_tmp_p, g_tmp);
    cudaGetSymbolAddress((void**)&g_agg_p, g_agg);
    cudaGetSymbolAddress((void**)&wbuf, g_wbuf);

    const uint4* w_enc1 = (const uint4*)(wbuf + 0);
    const uint4* w_enc2 = (const uint4*)(wbuf + 32768);

    const int SMEM = 98304;
    cudaFuncSetAttribute(fused_mlp_k<64,  false, false, false>, cudaFuncAttributeMaxDynamicSharedMemorySize, SMEM);
    cudaFuncSetAttribute(fused_mlp_k<128, false, true,  true >, cudaFuncAttributeMaxDynamicSharedMemorySize, SMEM);
    cudaFuncSetAttribute(fused_mlp_k<128, true,  true,  true >, cudaFuncAttributeMaxDynamicSharedMemorySize, SMEM);

    int gb_nodes = (n + 255) / 256;
    int gb_edges = (e + 255) / 256;
    int gb_gemm  = (n + 127) / 128;
    int gb_warp8 = (n + 7) / 8;

    // ---- launch order keeps the encoder fused MLP 4th for ncu ----
    zero_cnt_k<<<gb_nodes, 256>>>(n);                    // 1
    hist_k<<<gb_edges, 256>>>(dst, e);                   // 2
    wprep_k<<<76, 256>>>(enc_w1, enc_w2, mlp_w1, mlp_w2);// 3
    fused_mlp_k<64, false, false, false><<<gb_gemm, 512, SMEM>>>(  // 4 <- profiled
        x, nullptr, w_enc1, enc_b1, w_enc2, enc_b2, g_h_p, n);
    zero_stats_k<<<1, 128>>>();                          // 5
    scan1_k<<<gb_nodes, 256>>>(n);                       // 6
    scan2_k<<<1, 256>>>(gb_nodes);                       // 7
    scan3_k<<<gb_nodes, 256>>>(n);                       // 8 (also zeroes g_cnt)
    fill_k<<<gb_edges, 256>>>(src, dst, e);              // 9

    // ---- layers (z ping-pong: g_h -> g_tmp -> g_h -> ...) ----
    float* zin  = g_h_p;
    float* zout = g_tmp_p;
    for (int l = 0; l < 4; l++) {
        const uint4* w1s = (const uint4*)(wbuf + 98304 + l * 65536);
        const uint4* w2s = (const uint4*)(wbuf + 360448 + l * 65536);
        if (l == 0) {
            agg_k<false><<<gb_warp8, 256>>>(zin, edge_w + l * 8 * 128, edge_b + l * 128, ea, g_agg_p, n);
            fused_mlp_k<128, false, true, true><<<gb_gemm, 512, SMEM>>>(
                zin, g_agg_p, w1s, mlp_b1 + l * 128, w2s, mlp_b2 + l * 128, zout, n);
        } else {
            agg_k<true><<<gb_warp8, 256>>>(zin, edge_w + l * 8 * 128, edge_b + l * 128, ea, g_agg_p, n);
            fused_mlp_k<128, true, true, true><<<gb_gemm, 512, SMEM>>>(
                zin, g_agg_p, w1s, mlp_b1 + l * 128, w2s, mlp_b2 + l * 128, zout, n);
        }
        finalize_k<<<1, 128>>>(norm_w + l * 128, norm_b + l * 128, norm_a + l * 128,
                               1.f / (float)n);
        float* t = zin; zin = zout; zout = t;
    }
    // zin now holds z of layer 3
    decode_k<<<gb_warp8, 256>>>(zin, dec_w, dec_b, (float*)d_out, n);
}

// round 13
// speedup vs baseline: 1.0342x; 1.0342x over previous
#include <cuda_runtime.h>
#include <cuda_bf16.h>
#include <cstdint>

#define NMAX 50000
#define EMAX 600000
#define H 128

// ---------------- scratch (device globals; no allocation allowed) -------------
__device__ float g_h[NMAX * H];
__device__ float g_tmp[NMAX * H];
__device__ float g_agg[NMAX * H];
__device__ int   g_rptr[NMAX + 1];
__device__ int   g_cnt[NMAX];
__device__ int   g_part[256];
__device__ int2  g_csr[EMAX];
__device__ float g_sum[H];
__device__ float g_sumsq[H];
__device__ float g_scale[H];
__device__ float g_shift[H];
// pre-split weights: hi/lo bf16 planes in final swizzled layout
__device__ __align__(16) char g_wbuf[622592];

// ---------------- helpers -----------------------------------------------------
__device__ __forceinline__ uint32_t smem_to_u32(const void* p) {
    uint32_t a;
    asm("{ .reg .u64 t; cvta.to.shared.u64 t, %1; cvt.u32.u64 %0, t; }" : "=r"(a) : "l"(p));
    return a;
}

#define LDSM4(r0, r1, r2, r3, addr) \
    asm volatile("ldmatrix.sync.aligned.m8n8.x4.shared.b16 {%0,%1,%2,%3}, [%4];" \
        : "=r"(r0), "=r"(r1), "=r"(r2), "=r"(r3) : "r"(addr))

#define MMA16816(d, a, b0v, b1v) \
    asm volatile("mma.sync.aligned.m16n8k16.row.col.f32.bf16.bf16.f32 " \
        "{%0,%1,%2,%3},{%4,%5,%6,%7},{%8,%9},{%0,%1,%2,%3};" \
        : "+f"((d)[0]), "+f"((d)[1]), "+f"((d)[2]), "+f"((d)[3]) \
        : "r"((a)[0]), "r"((a)[1]), "r"((a)[2]), "r"((a)[3]), "r"(b0v), "r"(b1v))

__device__ __forceinline__ void cvt_pair(float a, float b, uint32_t& hi, uint32_t& lo) {
    __nv_bfloat16 ha = __float2bfloat16(a), hb = __float2bfloat16(b);
    __nv_bfloat16 la = __float2bfloat16(a - __bfloat162float(ha));
    __nv_bfloat16 lb = __float2bfloat16(b - __bfloat162float(hb));
    __nv_bfloat162 hp; hp.x = ha; hp.y = hb;
    __nv_bfloat162 lp; lp.x = la; lp.y = lb;
    hi = *reinterpret_cast<uint32_t*>(&hp);
    lo = *reinterpret_cast<uint32_t*>(&lp);
}

// 3-pass split MMA over one 64-K chunk; warp tile 32x32 (mi 2 x ni 4) [R9 form]
__device__ __forceinline__ void mma3pass(uint32_t sb, uint32_t aH, uint32_t aL,
                                         uint32_t bH, uint32_t bL,
                                         int rmb, int n0w, int lid,
                                         float acc[2][4][4])
{
    #pragma unroll
    for (int pass = 0; pass < 3; pass++) {
        uint32_t aoff = (pass == 2) ? aL : aH;
        uint32_t boff = (pass == 1) ? bL : bH;
        #pragma unroll
        for (int ks = 0; ks < 4; ks++) {
            int crow = ks * 2 + (lid >> 4);
            uint32_t af[2][4], bf[2][4];
            #pragma unroll
            for (int mi = 0; mi < 2; mi++) {
                int row = rmb + mi * 16 + (lid & 15);
                uint32_t ad = sb + aoff + row * 128 + ((crow ^ (row & 7)) << 4);
                LDSM4(af[mi][0], af[mi][1], af[mi][2], af[mi][3], ad);
            }
            #pragma unroll
            for (int bi = 0; bi < 2; bi++) {
                int rn = n0w + bi * 16 + (lid & 15);
                uint32_t bd = sb + boff + rn * 128 + ((crow ^ (rn & 7)) << 4);
                LDSM4(bf[bi][0], bf[bi][1], bf[bi][2], bf[bi][3], bd);
            }
            #pragma unroll
            for (int mi = 0; mi < 2; mi++)
                #pragma unroll
                for (int ni = 0; ni < 4; ni++) {
                    uint32_t b0v = bf[ni >> 1][ni & 1];
                    uint32_t b1v = bf[ni >> 1][(ni & 1) + 2];
                    MMA16816(acc[mi][ni], af[mi], b0v, b1v);
                }
        }
    }
}

// ---------------- weight pre-split kernel -------------------------------------
__global__ __launch_bounds__(256) void wprep_k(
    const float* __restrict__ enc_w1, const float* __restrict__ enc_w2,
    const float* __restrict__ mlp_w1, const float* __restrict__ mlp_w2)
{
    int g = blockIdx.x * 256 + threadIdx.x;
    const float* W;
    uint32_t bufoff;
    int local;
    if (g < 1024)       { W = enc_w1; bufoff = 0;     local = g; }
    else if (g < 3072)  { W = enc_w2; bufoff = 32768; local = g - 1024; }
    else if (g < 11264) {
        int l = (g - 3072) >> 11;
        W = mlp_w1 + l * 16384; bufoff = 98304 + l * 65536; local = (g - 3072) & 2047;
    } else if (g < 19456) {
        int l = (g - 11264) >> 11;
        W = mlp_w2 + l * 16384; bufoff = 360448 + l * 65536; local = (g - 11264) & 2047;
    } else return;

    int nn = local & 127;
    int t  = local >> 7;
    int ci = t >> 3, cc = t & 7;
    float v[8];
    #pragma unroll
    for (int j = 0; j < 8; j++)
        v[j] = W[(size_t)(ci * 64 + cc * 8 + j) * 128 + nn];
    uint4 hi, lo;
    cvt_pair(v[0], v[1], hi.x, lo.x);
    cvt_pair(v[2], v[3], hi.y, lo.y);
    cvt_pair(v[4], v[5], hi.z, lo.z);
    cvt_pair(v[6], v[7], hi.w, lo.w);
    uint32_t off = nn * 128 + ((cc ^ (nn & 7)) << 4);
    char* base = g_wbuf + bufoff + ci * 32768;
    *(uint4*)(base + off) = hi;
    *(uint4*)(base + 16384 + off) = lo;
}

// ---------------- block-scan helper (256 threads, inclusive) ------------------
__device__ __forceinline__ int block_scan_256(int v, int tid, int* wsum) {
    int lane = tid & 31, wid = tid >> 5;
    #pragma unroll
    for (int o = 1; o < 32; o <<= 1) {
        int t = __shfl_up_sync(0xffffffffu, v, o);
        if (lane >= o) v += t;
    }
    if (lane == 31) wsum[wid] = v;
    __syncthreads();
    if (wid == 0) {
        int s = (lane < 8) ? wsum[lane] : 0;
        #pragma unroll
        for (int o = 1; o < 8; o <<= 1) {
            int t = __shfl_up_sync(0xffffffffu, s, o);
            if (lane >= o) s += t;
        }
        if (lane < 8) wsum[lane] = s;
    }
    __syncthreads();
    if (wid > 0) v += wsum[wid - 1];
    return v;
}

// ---------------- CSR build ---------------------------------------------------
__global__ void zero_cnt_k(int n) {
    int i = blockIdx.x * blockDim.x + threadIdx.x;
    if (i < n) g_cnt[i] = 0;
}
__global__ void hist_k(const int* __restrict__ dst, int e) {
    int i = blockIdx.x * blockDim.x + threadIdx.x;
    if (i < e) atomicAdd(&g_cnt[dst[i]], 1);
}
__global__ __launch_bounds__(256) void scan1_k(int n) {
    __shared__ int wsum[32];
    int tid = threadIdx.x, lane = tid & 31, wid = tid >> 5;
    int i = blockIdx.x * 256 + tid;
    int v = (i < n) ? g_cnt[i] : 0;
    #pragma unroll
    for (int o = 16; o > 0; o >>= 1) v += __shfl_down_sync(0xffffffffu, v, o);
    if (lane == 0) wsum[wid] = v;
    __syncthreads();
    if (wid == 0) {
        int s = (lane < 8) ? wsum[lane] : 0;
        #pragma unroll
        for (int o = 4; o > 0; o >>= 1) s += __shfl_down_sync(0xffffffffu, s, o);
        if (lane == 0) g_part[blockIdx.x] = s;
    }
}
__global__ __launch_bounds__(256) void scan2_k(int nb) {
    __shared__ int wsum[32];
    int tid = threadIdx.x;
    int v = (tid < nb) ? g_part[tid] : 0;
    int inc = block_scan_256(v, tid, wsum);
    if (tid < nb) g_part[tid] = inc - v;
}
// scan3 also re-zeros g_cnt for fill_k (saves a separate zero pass)
__global__ __launch_bounds__(256) void scan3_k(int n) {
    __shared__ int wsum[32];
    int tid = threadIdx.x;
    int i = blockIdx.x * 256 + tid;
    int v = (i < n) ? g_cnt[i] : 0;
    int inc = block_scan_256(v, tid, wsum);
    if (i < n) {
        g_rptr[i + 1] = inc + g_part[blockIdx.x];
        g_cnt[i] = 0;
    }
    if (i == 0) g_rptr[0] = 0;
}
__global__ void fill_k(const int* __restrict__ src, const int* __restrict__ dst, int e) {
    int i = blockIdx.x * blockDim.x + threadIdx.x;
    if (i < e) {
        int d = dst[i];
        int p = g_rptr[d] + atomicAdd(&g_cnt[d], 1);
        g_csr[p] = make_int2(src[i], i);
    }
}

// ---------------- fused 2-layer MLP (512 threads, 32x32 warp tiles) -----------
template<int KA, bool NORM_A, bool ADD2>
__global__ __launch_bounds__(512) void fused_mlp_k(
    const float* __restrict__ Z, const float* __restrict__ AG,
    const uint4* __restrict__ w1s, const float* __restrict__ b1,
    const uint4* __restrict__ w2s, const float* __restrict__ b2,
    float* __restrict__ C, int M)
{
    extern __shared__ __align__(128) char smem[];
    uint32_t sb = smem_to_u32(smem);
    const uint32_t AH = 0, AL = 16384, BH = 32768;
    const uint32_t C1H = 0, C1L = 32768, B2H = 65536;

    int tid = threadIdx.x, lid = tid & 31, wid = tid >> 5;
    int m0 = blockIdx.x * 128;
    int rmb = (wid & 3) * 32;
    int n0w = (wid >> 2) * 32;
    int qr = lid >> 2, qc = lid & 3;

    float acc[2][4][4];
    #pragma unroll
    for (int mi = 0; mi < 2; mi++)
        #pragma unroll
        for (int ni = 0; ni < 4; ni++)
            #pragma unroll
            for (int j = 0; j < 4; j++) acc[mi][ni][j] = 0.f;

    // ================= GEMM 1 =================
    for (int kc = 0; kc < KA; kc += 64) {
        if (kc) __syncthreads();
        #pragma unroll
        for (int i = 0; i < 2; i++) {
            int cid = tid + i * 512;
            int r = cid >> 3, c = cid & 7;
            int gr = m0 + r;
            int col0 = kc + c * 8;
            float v[8];
            if (gr < M) {
                const float4* p = (const float4*)(Z + (size_t)gr * KA + col0);
                float4 v0 = p[0], v1 = p[1];
                v[0] = v0.x; v[1] = v0.y; v[2] = v0.z; v[3] = v0.w;
                v[4] = v1.x; v[5] = v1.y; v[6] = v1.z; v[7] = v1.w;
                if (NORM_A) {
                    float4 s0 = ((const float4*)g_scale)[col0 >> 2];
                    float4 s1 = ((const float4*)g_scale)[(col0 >> 2) + 1];
                    float4 t0 = ((const float4*)g_shift)[col0 >> 2];
                    float4 t1 = ((const float4*)g_shift)[(col0 >> 2) + 1];
                    v[0] = fmaxf(fmaf(v[0], s0.x, t0.x), 0.f);
                    v[1] = fmaxf(fmaf(v[1], s0.y, t0.y), 0.f);
                    v[2] = fmaxf(fmaf(v[2], s0.z, t0.z), 0.f);
                    v[3] = fmaxf(fmaf(v[3], s0.w, t0.w), 0.f);
                    v[4] = fmaxf(fmaf(v[4], s1.x, t1.x), 0.f);
                    v[5] = fmaxf(fmaf(v[5], s1.y, t1.y), 0.f);
                    v[6] = fmaxf(fmaf(v[6], s1.z, t1.z), 0.f);
                    v[7] = fmaxf(fmaf(v[7], s1.w, t1.w), 0.f);
                }
                if (ADD2) {
                    const float4* q = (const float4*)(AG + (size_t)gr * 128 + col0);
                    float4 w0 = q[0], w1 = q[1];
                    v[0] += w0.x; v[1] += w0.y; v[2] += w0.z; v[3] += w0.w;
                    v[4] += w1.x; v[5] += w1.y; v[6] += w1.z; v[7] += w1.w;
                }
            } else {
                #pragma unroll
                for (int j = 0; j < 8; j++) v[j] = 0.f;
            }
            uint4 hi, lo;
            cvt_pair(v[0], v[1], hi.x, lo.x);
            cvt_pair(v[2], v[3], hi.y, lo.y);
            cvt_pair(v[4], v[5], hi.z, lo.z);
            cvt_pair(v[6], v[7], hi.w, lo.w);
            uint32_t off = r * 128 + ((c ^ (r & 7)) << 4);
            *(uint4*)(smem + AH + off) = hi;
            *(uint4*)(smem + AL + off) = lo;
        }
        {
            const uint4* wp = w1s + (kc >> 6) * 2048;
            #pragma unroll
            for (int i = 0; i < 4; i++) {
                int idx = tid + i * 512;
                ((uint4*)(smem + BH))[idx] = wp[idx];
            }
        }
        __syncthreads();
        mma3pass(sb, AH, AL, BH, BH + 16384, rmb, n0w, lid, acc);
    }
    __syncthreads();

    // ================= C1 = relu(acc + b1) -> smem bf16 split =================
    #pragma unroll
    for (int ni = 0; ni < 4; ni++) {
        int col = n0w + ni * 8 + qc * 2;
        float bb0 = __ldg(b1 + col), bb1 = __ldg(b1 + col + 1);
        uint32_t plane = (uint32_t)(col >> 6) * 16384u;
        int cl = col & 63;
        int cc = cl >> 3;
        uint32_t cb = (uint32_t)((cl & 7) * 2);
        #pragma unroll
        for (int mi = 0; mi < 2; mi++) {
            int r0 = rmb + mi * 16 + qr;
            int r1 = r0 + 8;
            float o00 = fmaxf(acc[mi][ni][0] + bb0, 0.f);
            float o01 = fmaxf(acc[mi][ni][1] + bb1, 0.f);
            float o10 = fmaxf(acc[mi][ni][2] + bb0, 0.f);
            float o11 = fmaxf(acc[mi][ni][3] + bb1, 0.f);
            uint32_t h0, l0, h1, l1;
            cvt_pair(o00, o01, h0, l0);
            cvt_pair(o10, o11, h1, l1);
            uint32_t off0 = plane + r0 * 128 + ((cc ^ (r0 & 7)) << 4) + cb;
            uint32_t off1 = plane + r1 * 128 + ((cc ^ (r1 & 7)) << 4) + cb;
            *(uint32_t*)(smem + C1H + off0) = h0;
            *(uint32_t*)(smem + C1L + off0) = l0;
            *(uint32_t*)(smem + C1H + off1) = h1;
            *(uint32_t*)(smem + C1L + off1) = l1;
        }
    }
    #pragma unroll
    for (int mi = 0; mi < 2; mi++)
        #pragma unroll
        for (int ni = 0; ni < 4; ni++)
            #pragma unroll
            for (int j = 0; j < 4; j++) acc[mi][ni][j] = 0.f;

    // ================= GEMM 2 (K = 128, A = C1 in smem) =================
    for (int kc = 0; kc < 128; kc += 64) {
        if (kc) __syncthreads();
        {
            const uint4* wp = w2s + (kc >> 6) * 2048;
            #pragma unroll
            for (int i = 0; i < 4; i++) {
                int idx = tid + i * 512;
                ((uint4*)(smem + B2H))[idx] = wp[idx];
            }
        }
        __syncthreads();
        uint32_t plane = (uint32_t)(kc >> 6) * 16384u;
        mma3pass(sb, C1H + plane, C1L + plane, B2H, B2H + 16384, rmb, n0w, lid, acc);
    }

    // ================= epilogue: z = acc + b2 (no relu) =================
    #pragma unroll
    for (int ni = 0; ni < 4; ni++) {
        int col = n0w + ni * 8 + qc * 2;
        float b0 = __ldg(b2 + col), b1v = __ldg(b2 + col + 1);
        #pragma unroll
        for (int mi = 0; mi < 2; mi++) {
            int gr = m0 + rmb + mi * 16 + qr;
            float2 o0 = make_float2(acc[mi][ni][0] + b0, acc[mi][ni][1] + b1v);
            float2 o1 = make_float2(acc[mi][ni][2] + b0, acc[mi][ni][3] + b1v);
            if (gr < M)     *(float2*)(C + (size_t)gr * 128 + col) = o0;
            if (gr + 8 < M) *(float2*)(C + (size_t)(gr + 8) * 128 + col) = o1;
        }
    }
}

// ---------------- GINE aggregate (warp/node, 2-edge unrolled loads) -----------
template<bool NORM>
__global__ __launch_bounds__(256) void agg_k(
    const float* __restrict__ h, const float* __restrict__ We,
    const float* __restrict__ be, const float* __restrict__ ea,
    float* __restrict__ out, int n)
{
    int lane = threadIdx.x & 31;
    int node = blockIdx.x * 8 + (threadIdx.x >> 5);

    const float4* We4 = (const float4*)We;
    float4 w[8];
    #pragma unroll
    for (int k = 0; k < 8; k++) w[k] = We4[k * 32 + lane];
    float4 bev = ((const float4*)be)[lane];
    float4 sc, sh;
    if (NORM) {
        sc = ((const float4*)g_scale)[lane];
        sh = ((const float4*)g_shift)[lane];
    }

    if (node >= n) return;
    int s = g_rptr[node], e = g_rptr[node + 1];

    const float4* h4  = (const float4*)h;
    const float4* ea4 = (const float4*)ea;
    float4 acc = make_float4(0.f, 0.f, 0.f, 0.f);

    #define NORM_HV(hv) do { if (NORM) { \
        hv.x = fmaxf(fmaf(hv.x, sc.x, sh.x), 0.f); \
        hv.y = fmaxf(fmaf(hv.y, sc.y, sh.y), 0.f); \
        hv.z = fmaxf(fmaf(hv.z, sc.z, sh.z), 0.f); \
        hv.w = fmaxf(fmaf(hv.w, sc.w, sh.w), 0.f); } } while (0)
    #define EDGE_BODY(a0, a1, hv) do { \
        float4 lin = bev; \
        lin.x = fmaf(a0.x, w[0].x, lin.x); lin.y = fmaf(a0.x, w[0].y, lin.y); \
        lin.z = fmaf(a0.x, w[0].z, lin.z); lin.w = fmaf(a0.x, w[0].w, lin.w); \
        lin.x = fmaf(a0.y, w[1].x, lin.x); lin.y = fmaf(a0.y, w[1].y, lin.y); \
        lin.z = fmaf(a0.y, w[1].z, lin.z); lin.w = fmaf(a0.y, w[1].w, lin.w); \
        lin.x = fmaf(a0.z, w[2].x, lin.x); lin.y = fmaf(a0.z, w[2].y, lin.y); \
        lin.z = fmaf(a0.z, w[2].z, lin.z); lin.w = fmaf(a0.z, w[2].w, lin.w); \
        lin.x = fmaf(a0.w, w[3].x, lin.x); lin.y = fmaf(a0.w, w[3].y, lin.y); \
        lin.z = fmaf(a0.w, w[3].z, lin.z); lin.w = fmaf(a0.w, w[3].w, lin.w); \
        lin.x = fmaf(a1.x, w[4].x, lin.x); lin.y = fmaf(a1.x, w[4].y, lin.y); \
        lin.z = fmaf(a1.x, w[4].z, lin.z); lin.w = fmaf(a1.x, w[4].w, lin.w); \
        lin.x = fmaf(a1.y, w[5].x, lin.x); lin.y = fmaf(a1.y, w[5].y, lin.y); \
        lin.z = fmaf(a1.y, w[5].z, lin.z); lin.w = fmaf(a1.y, w[5].w, lin.w); \
        lin.x = fmaf(a1.z, w[6].x, lin.x); lin.y = fmaf(a1.z, w[6].y, lin.y); \
        lin.z = fmaf(a1.z, w[6].z, lin.z); lin.w = fmaf(a1.z, w[6].w, lin.w); \
        lin.x = fmaf(a1.w, w[7].x, lin.x); lin.y = fmaf(a1.w, w[7].y, lin.y); \
        lin.z = fmaf(a1.w, w[7].z, lin.z); lin.w = fmaf(a1.w, w[7].w, lin.w); \
        acc.x += fmaxf(hv.x + lin.x, 0.f); \
        acc.y += fmaxf(hv.y + lin.y, 0.f); \
        acc.z += fmaxf(hv.z + lin.z, 0.f); \
        acc.w += fmaxf(hv.w + lin.w, 0.f); } while (0)

    int i = s;
    for (; i + 1 < e; i += 2) {
        // batch all loads for 2 edges before any compute (MLP 6)
        int2 se0 = g_csr[i];
        int2 se1 = g_csr[i + 1];
        float4 p0 = ea4[se0.y * 2];
        float4 p1 = ea4[se0.y * 2 + 1];
        float4 q0 = ea4[se1.y * 2];
        float4 q1 = ea4[se1.y * 2 + 1];
        float4 h0 = h4[se0.x * 32 + lane];
        float4 h1 = h4[se1.x * 32 + lane];
        NORM_HV(h0);
        NORM_HV(h1);
        EDGE_BODY(p0, p1, h0);
        EDGE_BODY(q0, q1, h1);
    }
    if (i < e) {
        int2 se0 = g_csr[i];
        float4 p0 = ea4[se0.y * 2];
        float4 p1 = ea4[se0.y * 2 + 1];
        float4 h0 = h4[se0.x * 32 + lane];
        NORM_HV(h0);
        EDGE_BODY(p0, p1, h0);
    }
    #undef NORM_HV
    #undef EDGE_BODY
    ((float4*)out)[node * 32 + lane] = acc;
}

// ---------------- GraphNorm ---------------------------------------------------
__global__ void zero_stats_k() {
    int c = threadIdx.x;
    g_sum[c] = 0.f;
    g_sumsq[c] = 0.f;
}

__global__ __launch_bounds__(256) void stats_k(const float* __restrict__ z, int n) {
    __shared__ float red1[8][128];
    __shared__ float red2[8][128];
    int tid = threadIdx.x, w = tid >> 5, l = tid & 31;
    float4 s = make_float4(0.f, 0.f, 0.f, 0.f);
    float4 q = make_float4(0.f, 0.f, 0.f, 0.f);
    for (int r = blockIdx.x * 8 + w; r < n; r += gridDim.x * 8) {
        float4 v = ((const float4*)z)[(size_t)r * 32 + l];
        s.x += v.x; s.y += v.y; s.z += v.z; s.w += v.w;
        q.x += v.x * v.x; q.y += v.y * v.y; q.z += v.z * v.z; q.w += v.w * v.w;
    }
    ((float4*)&red1[w][0])[l] = s;
    ((float4*)&red2[w][0])[l] = q;
    __syncthreads();
    if (tid < 128) {
        float a = 0.f, b = 0.f;
        #pragma unroll
        for (int t = 0; t < 8; t++) { a += red1[t][tid]; b += red2[t][tid]; }
        atomicAdd(&g_sum[tid], a);
        atomicAdd(&g_sumsq[tid], b);
    }
}

__global__ void finalize_k(const float* __restrict__ nw, const float* __restrict__ nb,
                           const float* __restrict__ na, float inv_n)
{
    int c = threadIdx.x;
    float s = g_sum[c], q = g_sumsq[c];
    g_sum[c] = 0.f;
    g_sumsq[c] = 0.f;
    float mu  = s * inv_n;
    float ez2 = q * inv_n;
    float a = na[c];
    float var = ez2 - (2.f * a - a * a) * mu * mu;
    float inv = rsqrtf(var + 1e-5f);
    g_scale[c] = nw[c] * inv;
    g_shift[c] = nb[c] - nw[c] * inv * a * mu;
}

__global__ __launch_bounds__(256) void decode_k(
    const float* __restrict__ z, const float* __restrict__ dec_w,
    const float* __restrict__ dec_b, float* __restrict__ out, int n)
{
    int lane = threadIdx.x & 31;
    int node = blockIdx.x * 8 + (threadIdx.x >> 5);
    if (node >= n) return;
    float4 sc = ((const float4*)g_scale)[lane];
    float4 sh = ((const float4*)g_shift)[lane];
    float4 zv = ((const float4*)z)[node * 32 + lane];
    float4 hv;
    hv.x = fmaxf(fmaf(zv.x, sc.x, sh.x), 0.f);
    hv.y = fmaxf(fmaf(zv.y, sc.y, sh.y), 0.f);
    hv.z = fmaxf(fmaf(zv.z, sc.z, sh.z), 0.f);
    hv.w = fmaxf(fmaf(zv.w, sc.w, sh.w), 0.f);
    float4 dw = ((const float4*)dec_w)[lane];
    float p = hv.x * dw.x + hv.y * dw.y + hv.z * dw.z + hv.w * dw.w;
    #pragma unroll
    for (int o = 16; o > 0; o >>= 1) p += __shfl_down_sync(0xffffffffu, p, o);
    if (lane == 0) out[node] = p + dec_b[0];
}

// ---------------- launch ------------------------------------------------------
extern "C" void kernel_launch(void* const* d_in, const int* in_sizes, int n_in,
                              void* d_out, int out_size)
{
    const float* x      = (const float*)d_in[0];
    const int*   ei     = (const int*)d_in[1];
    const float* ea     = (const float*)d_in[2];
    const float* enc_w1 = (const float*)d_in[3];
    const float* enc_b1 = (const float*)d_in[4];
    const float* enc_w2 = (const float*)d_in[5];
    const float* enc_b2 = (const float*)d_in[6];
    const float* edge_w = (const float*)d_in[7];
    const float* edge_b = (const float*)d_in[8];
    const float* mlp_w1 = (const float*)d_in[9];
    const float* mlp_b1 = (const float*)d_in[10];
    const float* mlp_w2 = (const float*)d_in[11];
    const float* mlp_b2 = (const float*)d_in[12];
    const float* norm_w = (const float*)d_in[13];
    const float* norm_b = (const float*)d_in[14];
    const float* norm_a = (const float*)d_in[15];
    const float* dec_w  = (const float*)d_in[16];
    const float* dec_b  = (const float*)d_in[17];

    int n = in_sizes[0] / 64;
    int e = in_sizes[2] / 8;
    const int* src = ei;
    const int* dst = ei + e;

    float *g_h_p, *g_tmp_p, *g_agg_p;
    char* wbuf;
    cudaGetSymbolAddress((void**)&g_h_p, g_h);
    cudaGetSymbolAddress((void**)&g_tmp_p, g_tmp);
    cudaGetSymbolAddress((void**)&g_agg_p, g_agg);
    cudaGetSymbolAddress((void**)&wbuf, g_wbuf);

    const uint4* w_enc1 = (const uint4*)(wbuf + 0);
    const uint4* w_enc2 = (const uint4*)(wbuf + 32768);

    const int SMEM = 98304;
    cudaFuncSetAttribute(fused_mlp_k<64,  false, false>, cudaFuncAttributeMaxDynamicSharedMemorySize, SMEM);
    cudaFuncSetAttribute(fused_mlp_k<128, false, true >, cudaFuncAttributeMaxDynamicSharedMemorySize, SMEM);
    cudaFuncSetAttribute(fused_mlp_k<128, true,  true >, cudaFuncAttributeMaxDynamicSharedMemorySize, SMEM);

    int gb_nodes = (n + 255) / 256;
    int gb_edges = (e + 255) / 256;
    int gb_gemm  = (n + 127) / 128;
    int gb_warp8 = (n + 7) / 8;

    // ---- launch order keeps the encoder fused MLP 4th for ncu ----
    zero_cnt_k<<<gb_nodes, 256>>>(n);                    // 1
    hist_k<<<gb_edges, 256>>>(dst, e);                   // 2
    wprep_k<<<76, 256>>>(enc_w1, enc_w2, mlp_w1, mlp_w2);// 3
    fused_mlp_k<64, false, false><<<gb_gemm, 512, SMEM>>>(   // 4  <- profiled
        x, nullptr, w_enc1, enc_b1, w_enc2, enc_b2, g_h_p, n);
    zero_stats_k<<<1, 128>>>();                          // 5
    scan1_k<<<gb_nodes, 256>>>(n);                       // 6
    scan2_k<<<1, 256>>>(gb_nodes);                       // 7
    scan3_k<<<gb_nodes, 256>>>(n);                       // 8 (also zeroes g_cnt)
    fill_k<<<gb_edges, 256>>>(src, dst, e);              // 9

    // ---- layers (z ping-pong: g_h -> g_tmp -> g_h -> ...) ----
    float* zin  = g_h_p;
    float* zout = g_tmp_p;
    for (int l = 0; l < 4; l++) {
        const uint4* w1s = (const uint4*)(wbuf + 98304 + l * 65536);
        const uint4* w2s = (const uint4*)(wbuf + 360448 + l * 65536);
        if (l == 0) {
            agg_k<false><<<gb_warp8, 256>>>(zin, edge_w + l * 8 * 128, edge_b + l * 128, ea, g_agg_p, n);
            fused_mlp_k<128, false, true><<<gb_gemm, 512, SMEM>>>(
                zin, g_agg_p, w1s, mlp_b1 + l * 128, w2s, mlp_b2 + l * 128, zout, n);
        } else {
            agg_k<true><<<gb_warp8, 256>>>(zin, edge_w + l * 8 * 128, edge_b + l * 128, ea, g_agg_p, n);
            fused_mlp_k<128, true, true><<<gb_gemm, 512, SMEM>>>(
                zin, g_agg_p, w1s, mlp_b1 + l * 128, w2s, mlp_b2 + l * 128, zout, n);
        }
        stats_k<<<256, 256>>>(zout, n);
        finalize_k<<<1, 128>>>(norm_w + l * 128, norm_b + l * 128, norm_a + l * 128,
                               1.f / (float)n);
        float* t = zin; zin = zout; zout = t;
    }
    // zin now holds z of layer 3
    decode_k<<<gb_warp8, 256>>>(zin, dec_w, dec_b, (float*)d_out, n);
}

// round 15
// speedup vs baseline: 1.1916x; 1.1522x over previous
#include <cuda_runtime.h>
#include <cuda_bf16.h>
#include <cstdint>

#define NMAX 50000
#define EMAX 600000
#define H 128

// ---------------- scratch (device globals; no allocation allowed) -------------
__device__ float g_h[NMAX * H];
__device__ float g_tmp[NMAX * H];
__device__ float g_agg[NMAX * H];
__device__ int   g_rptr[NMAX + 1];
__device__ int   g_cnt[NMAX];
__device__ int   g_part[256];
__device__ int2  g_csr[EMAX];
__device__ float g_sum[H];
__device__ float g_sumsq[H];
__device__ float g_scale[H];
__device__ float g_shift[H];
// pre-split weights: hi/lo bf16 planes in final swizzled layout
__device__ __align__(16) char g_wbuf[622592];

// ---------------- helpers -----------------------------------------------------
__device__ __forceinline__ uint32_t smem_to_u32(const void* p) {
    uint32_t a;
    asm("{ .reg .u64 t; cvta.to.shared.u64 t, %1; cvt.u32.u64 %0, t; }" : "=r"(a) : "l"(p));
    return a;
}

#define LDSM4(r0, r1, r2, r3, addr) \
    asm volatile("ldmatrix.sync.aligned.m8n8.x4.shared.b16 {%0,%1,%2,%3}, [%4];" \
        : "=r"(r0), "=r"(r1), "=r"(r2), "=r"(r3) : "r"(addr))

#define MMA16816(d, a, b0v, b1v) \
    asm volatile("mma.sync.aligned.m16n8k16.row.col.f32.bf16.bf16.f32 " \
        "{%0,%1,%2,%3},{%4,%5,%6,%7},{%8,%9},{%0,%1,%2,%3};" \
        : "+f"((d)[0]), "+f"((d)[1]), "+f"((d)[2]), "+f"((d)[3]) \
        : "r"((a)[0]), "r"((a)[1]), "r"((a)[2]), "r"((a)[3]), "r"(b0v), "r"(b1v))

__device__ __forceinline__ void cvt_pair(float a, float b, uint32_t& hi, uint32_t& lo) {
    __nv_bfloat16 ha = __float2bfloat16(a), hb = __float2bfloat16(b);
    __nv_bfloat16 la = __float2bfloat16(a - __bfloat162float(ha));
    __nv_bfloat16 lb = __float2bfloat16(b - __bfloat162float(hb));
    __nv_bfloat162 hp; hp.x = ha; hp.y = hb;
    __nv_bfloat162 lp; lp.x = la; lp.y = lb;
    hi = *reinterpret_cast<uint32_t*>(&hp);
    lo = *reinterpret_cast<uint32_t*>(&lp);
}

// 3-pass split MMA over one 64-K chunk; warp tile 32x32 (mi 2 x ni 4) [R9 form]
__device__ __forceinline__ void mma3pass(uint32_t sb, uint32_t aH, uint32_t aL,
                                         uint32_t bH, uint32_t bL,
                                         int rmb, int n0w, int lid,
                                         float acc[2][4][4])
{
    #pragma unroll
    for (int pass = 0; pass < 3; pass++) {
        uint32_t aoff = (pass == 2) ? aL : aH;
        uint32_t boff = (pass == 1) ? bL : bH;
        #pragma unroll
        for (int ks = 0; ks < 4; ks++) {
            int crow = ks * 2 + (lid >> 4);
            uint32_t af[2][4], bf[2][4];
            #pragma unroll
            for (int mi = 0; mi < 2; mi++) {
                int row = rmb + mi * 16 + (lid & 15);
                uint32_t ad = sb + aoff + row * 128 + ((crow ^ (row & 7)) << 4);
                LDSM4(af[mi][0], af[mi][1], af[mi][2], af[mi][3], ad);
            }
            #pragma unroll
            for (int bi = 0; bi < 2; bi++) {
                int rn = n0w + bi * 16 + (lid & 15);
                uint32_t bd = sb + boff + rn * 128 + ((crow ^ (rn & 7)) << 4);
                LDSM4(bf[bi][0], bf[bi][1], bf[bi][2], bf[bi][3], bd);
            }
            #pragma unroll
            for (int mi = 0; mi < 2; mi++)
                #pragma unroll
                for (int ni = 0; ni < 4; ni++) {
                    uint32_t b0v = bf[ni >> 1][ni & 1];
                    uint32_t b1v = bf[ni >> 1][(ni & 1) + 2];
                    MMA16816(acc[mi][ni], af[mi], b0v, b1v);
                }
        }
    }
}

// ---------------- weight pre-split kernel -------------------------------------
__global__ __launch_bounds__(256) void wprep_k(
    const float* __restrict__ enc_w1, const float* __restrict__ enc_w2,
    const float* __restrict__ mlp_w1, const float* __restrict__ mlp_w2)
{
    int g = blockIdx.x * 256 + threadIdx.x;
    const float* W;
    uint32_t bufoff;
    int local;
    if (g < 1024)       { W = enc_w1; bufoff = 0;     local = g; }
    else if (g < 3072)  { W = enc_w2; bufoff = 32768; local = g - 1024; }
    else if (g < 11264) {
        int l = (g - 3072) >> 11;
        W = mlp_w1 + l * 16384; bufoff = 98304 + l * 65536; local = (g - 3072) & 2047;
    } else if (g < 19456) {
        int l = (g - 11264) >> 11;
        W = mlp_w2 + l * 16384; bufoff = 360448 + l * 65536; local = (g - 11264) & 2047;
    } else return;

    int nn = local & 127;
    int t  = local >> 7;
    int ci = t >> 3, cc = t & 7;
    float v[8];
    #pragma unroll
    for (int j = 0; j < 8; j++)
        v[j] = W[(size_t)(ci * 64 + cc * 8 + j) * 128 + nn];
    uint4 hi, lo;
    cvt_pair(v[0], v[1], hi.x, lo.x);
    cvt_pair(v[2], v[3], hi.y, lo.y);
    cvt_pair(v[4], v[5], hi.z, lo.z);
    cvt_pair(v[6], v[7], hi.w, lo.w);
    uint32_t off = nn * 128 + ((cc ^ (nn & 7)) << 4);
    char* base = g_wbuf + bufoff + ci * 32768;
    *(uint4*)(base + off) = hi;
    *(uint4*)(base + 16384 + off) = lo;
}

// ---------------- block-scan helper (256 threads, inclusive) ------------------
__device__ __forceinline__ int block_scan_256(int v, int tid, int* wsum) {
    int lane = tid & 31, wid = tid >> 5;
    #pragma unroll
    for (int o = 1; o < 32; o <<= 1) {
        int t = __shfl_up_sync(0xffffffffu, v, o);
        if (lane >= o) v += t;
    }
    if (lane == 31) wsum[wid] = v;
    __syncthreads();
    if (wid == 0) {
        int s = (lane < 8) ? wsum[lane] : 0;
        #pragma unroll
        for (int o = 1; o < 8; o <<= 1) {
            int t = __shfl_up_sync(0xffffffffu, s, o);
            if (lane >= o) s += t;
        }
        if (lane < 8) wsum[lane] = s;
    }
    __syncthreads();
    if (wid > 0) v += wsum[wid - 1];
    return v;
}

// ---------------- CSR build ---------------------------------------------------
__global__ void zero_cnt_k(int n) {
    int i = blockIdx.x * blockDim.x + threadIdx.x;
    if (i < n) g_cnt[i] = 0;
}
__global__ void hist_k(const int* __restrict__ dst, int e) {
    int i = blockIdx.x * blockDim.x + threadIdx.x;
    if (i < e) atomicAdd(&g_cnt[dst[i]], 1);
}
__global__ __launch_bounds__(256) void scan1_k(int n) {
    __shared__ int wsum[32];
    int tid = threadIdx.x, lane = tid & 31, wid = tid >> 5;
    int i = blockIdx.x * 256 + tid;
    int v = (i < n) ? g_cnt[i] : 0;
    #pragma unroll
    for (int o = 16; o > 0; o >>= 1) v += __shfl_down_sync(0xffffffffu, v, o);
    if (lane == 0) wsum[wid] = v;
    __syncthreads();
    if (wid == 0) {
        int s = (lane < 8) ? wsum[lane] : 0;
        #pragma unroll
        for (int o = 4; o > 0; o >>= 1) s += __shfl_down_sync(0xffffffffu, s, o);
        if (lane == 0) g_part[blockIdx.x] = s;
    }
}
__global__ __launch_bounds__(256) void scan2_k(int nb) {
    __shared__ int wsum[32];
    int tid = threadIdx.x;
    int v = (tid < nb) ? g_part[tid] : 0;
    int inc = block_scan_256(v, tid, wsum);
    if (tid < nb) g_part[tid] = inc - v;
}
// scan3 also re-zeros g_cnt for fill_k (saves a separate zero pass)
__global__ __launch_bounds__(256) void scan3_k(int n) {
    __shared__ int wsum[32];
    int tid = threadIdx.x;
    int i = blockIdx.x * 256 + tid;
    int v = (i < n) ? g_cnt[i] : 0;
    int inc = block_scan_256(v, tid, wsum);
    if (i < n) {
        g_rptr[i + 1] = inc + g_part[blockIdx.x];
        g_cnt[i] = 0;
    }
    if (i == 0) g_rptr[0] = 0;
}
__global__ void fill_k(const int* __restrict__ src, const int* __restrict__ dst, int e) {
    int i = blockIdx.x * blockDim.x + threadIdx.x;
    if (i < e) {
        int d = dst[i];
        int p = g_rptr[d] + atomicAdd(&g_cnt[d], 1);
        g_csr[p] = make_int2(src[i], i);
    }
}

// ---------------- fused 2-layer MLP (512 threads, 32x32 warp tiles) -----------
// A comes pre-combined (agg output already includes the normalized self term),
// so staging is a single straight read + split.
template<int KA>
__global__ __launch_bounds__(512) void fused_mlp_k(
    const float* __restrict__ Z,
    const uint4* __restrict__ w1s, const float* __restrict__ b1,
    const uint4* __restrict__ w2s, const float* __restrict__ b2,
    float* __restrict__ C, int M)
{
    extern __shared__ __align__(128) char smem[];
    uint32_t sb = smem_to_u32(smem);
    const uint32_t AH = 0, AL = 16384, BH = 32768;
    const uint32_t C1H = 0, C1L = 32768, B2H = 65536;

    int tid = threadIdx.x, lid = tid & 31, wid = tid >> 5;
    int m0 = blockIdx.x * 128;
    int rmb = (wid & 3) * 32;
    int n0w = (wid >> 2) * 32;
    int qr = lid >> 2, qc = lid & 3;

    float acc[2][4][4];
    #pragma unroll
    for (int mi = 0; mi < 2; mi++)
        #pragma unroll
        for (int ni = 0; ni < 4; ni++)
            #pragma unroll
            for (int j = 0; j < 4; j++) acc[mi][ni][j] = 0.f;

    // ================= GEMM 1 =================
    for (int kc = 0; kc < KA; kc += 64) {
        if (kc) __syncthreads();
        #pragma unroll
        for (int i = 0; i < 2; i++) {
            int cid = tid + i * 512;
            int r = cid >> 3, c = cid & 7;
            int gr = m0 + r;
            int col0 = kc + c * 8;
            float v[8];
            if (gr < M) {
                const float4* p = (const float4*)(Z + (size_t)gr * KA + col0);
                float4 v0 = p[0], v1 = p[1];
                v[0] = v0.x; v[1] = v0.y; v[2] = v0.z; v[3] = v0.w;
                v[4] = v1.x; v[5] = v1.y; v[6] = v1.z; v[7] = v1.w;
            } else {
                #pragma unroll
                for (int j = 0; j < 8; j++) v[j] = 0.f;
            }
            uint4 hi, lo;
            cvt_pair(v[0], v[1], hi.x, lo.x);
            cvt_pair(v[2], v[3], hi.y, lo.y);
            cvt_pair(v[4], v[5], hi.z, lo.z);
            cvt_pair(v[6], v[7], hi.w, lo.w);
            uint32_t off = r * 128 + ((c ^ (r & 7)) << 4);
            *(uint4*)(smem + AH + off) = hi;
            *(uint4*)(smem + AL + off) = lo;
        }
        {
            const uint4* wp = w1s + (kc >> 6) * 2048;
            #pragma unroll
            for (int i = 0; i < 4; i++) {
                int idx = tid + i * 512;
                ((uint4*)(smem + BH))[idx] = wp[idx];
            }
        }
        __syncthreads();
        mma3pass(sb, AH, AL, BH, BH + 16384, rmb, n0w, lid, acc);
    }
    __syncthreads();

    // ================= C1 = relu(acc + b1) -> smem bf16 split =================
    #pragma unroll
    for (int ni = 0; ni < 4; ni++) {
        int col = n0w + ni * 8 + qc * 2;
        float bb0 = __ldg(b1 + col), bb1 = __ldg(b1 + col + 1);
        uint32_t plane = (uint32_t)(col >> 6) * 16384u;
        int cl = col & 63;
        int cc = cl >> 3;
        uint32_t cb = (uint32_t)((cl & 7) * 2);
        #pragma unroll
        for (int mi = 0; mi < 2; mi++) {
            int r0 = rmb + mi * 16 + qr;
            int r1 = r0 + 8;
            float o00 = fmaxf(acc[mi][ni][0] + bb0, 0.f);
            float o01 = fmaxf(acc[mi][ni][1] + bb1, 0.f);
            float o10 = fmaxf(acc[mi][ni][2] + bb0, 0.f);
            float o11 = fmaxf(acc[mi][ni][3] + bb1, 0.f);
            uint32_t h0, l0, h1, l1;
            cvt_pair(o00, o01, h0, l0);
            cvt_pair(o10, o11, h1, l1);
            uint32_t off0 = plane + r0 * 128 + ((cc ^ (r0 & 7)) << 4) + cb;
            uint32_t off1 = plane + r1 * 128 + ((cc ^ (r1 & 7)) << 4) + cb;
            *(uint32_t*)(smem + C1H + off0) = h0;
            *(uint32_t*)(smem + C1L + off0) = l0;
            *(uint32_t*)(smem + C1H + off1) = h1;
            *(uint32_t*)(smem + C1L + off1) = l1;
        }
    }
    #pragma unroll
    for (int mi = 0; mi < 2; mi++)
        #pragma unroll
        for (int ni = 0; ni < 4; ni++)
            #pragma unroll
            for (int j = 0; j < 4; j++) acc[mi][ni][j] = 0.f;

    // ================= GEMM 2 (K = 128, A = C1 in smem) =================
    for (int kc = 0; kc < 128; kc += 64) {
        if (kc) __syncthreads();
        {
            const uint4* wp = w2s + (kc >> 6) * 2048;
            #pragma unroll
            for (int i = 0; i < 4; i++) {
                int idx = tid + i * 512;
                ((uint4*)(smem + B2H))[idx] = wp[idx];
            }
        }
        __syncthreads();
        uint32_t plane = (uint32_t)(kc >> 6) * 16384u;
        mma3pass(sb, C1H + plane, C1L + plane, B2H, B2H + 16384, rmb, n0w, lid, acc);
    }

    // ================= epilogue: z = acc + b2 (no relu) =================
    #pragma unroll
    for (int ni = 0; ni < 4; ni++) {
        int col = n0w + ni * 8 + qc * 2;
        float b0 = __ldg(b2 + col), b1v = __ldg(b2 + col + 1);
        #pragma unroll
        for (int mi = 0; mi < 2; mi++) {
            int gr = m0 + rmb + mi * 16 + qr;
            float2 o0 = make_float2(acc[mi][ni][0] + b0, acc[mi][ni][1] + b1v);
            float2 o1 = make_float2(acc[mi][ni][2] + b0, acc[mi][ni][3] + b1v);
            if (gr < M)     *(float2*)(C + (size_t)gr * 128 + col) = o0;
            if (gr + 8 < M) *(float2*)(C + (size_t)(gr + 8) * 128 + col) = o1;
        }
    }
}

// ---------------- GINE aggregate (CSR, warp per node, plain R9 loop) ----------
// Output = h_node + sum_edges relu(h_src + lin(ea)), h = NORM ? relu(z*sc+sh) : z.
// The self term folds the MLP's old (x_i + agg) add into this kernel, so the
// MLP stages from a single buffer.
template<bool NORM>
__global__ __launch_bounds__(256) void agg_k(
    const float* __restrict__ h, const float* __restrict__ We,
    const float* __restrict__ be, const float* __restrict__ ea,
    float* __restrict__ out, int n)
{
    int lane = threadIdx.x & 31;
    int node = blockIdx.x * 8 + (threadIdx.x >> 5);

    const float4* We4 = (const float4*)We;
    float4 w[8];
    #pragma unroll
    for (int k = 0; k < 8; k++) w[k] = We4[k * 32 + lane];
    float4 bev = ((const float4*)be)[lane];
    float4 sc, sh;
    if (NORM) {
        sc = ((const float4*)g_scale)[lane];
        sh = ((const float4*)g_shift)[lane];
    }

    if (node >= n) return;
    int s = g_rptr[node], e = g_rptr[node + 1];

    const float4* h4  = (const float4*)h;
    const float4* ea4 = (const float4*)ea;

    // self term: h_node (normalized) — z_i = h_i + agg_i
    float4 acc = h4[node * 32 + lane];
    if (NORM) {
        acc.x = fmaxf(fmaf(acc.x, sc.x, sh.x), 0.f);
        acc.y = fmaxf(fmaf(acc.y, sc.y, sh.y), 0.f);
        acc.z = fmaxf(fmaf(acc.z, sc.z, sh.z), 0.f);
        acc.w = fmaxf(fmaf(acc.w, sc.w, sh.w), 0.f);
    }

    for (int i = s; i < e; i++) {
        int2 se = g_csr[i];
        float4 a0 = ea4[se.y * 2];
        float4 a1 = ea4[se.y * 2 + 1];
        float4 hv = h4[se.x * 32 + lane];
        if (NORM) {
            hv.x = fmaxf(fmaf(hv.x, sc.x, sh.x), 0.f);
            hv.y = fmaxf(fmaf(hv.y, sc.y, sh.y), 0.f);
            hv.z = fmaxf(fmaf(hv.z, sc.z, sh.z), 0.f);
            hv.w = fmaxf(fmaf(hv.w, sc.w, sh.w), 0.f);
        }
        float4 lin = bev;
        #define ACCW(comp, wi) \
            lin.x = fmaf(comp, w[wi].x, lin.x); lin.y = fmaf(comp, w[wi].y, lin.y); \
            lin.z = fmaf(comp, w[wi].z, lin.z); lin.w = fmaf(comp, w[wi].w, lin.w);
        ACCW(a0.x, 0) ACCW(a0.y, 1) ACCW(a0.z, 2) ACCW(a0.w, 3)
        ACCW(a1.x, 4) ACCW(a1.y, 5) ACCW(a1.z, 6) ACCW(a1.w, 7)
        #undef ACCW
        acc.x += fmaxf(hv.x + lin.x, 0.f);
        acc.y += fmaxf(hv.y + lin.y, 0.f);
        acc.z += fmaxf(hv.z + lin.z, 0.f);
        acc.w += fmaxf(hv.w + lin.w, 0.f);
    }
    ((float4*)out)[node * 32 + lane] = acc;
}

// ---------------- GraphNorm ---------------------------------------------------
__global__ void zero_stats_k() {
    int c = threadIdx.x;
    g_sum[c] = 0.f;
    g_sumsq[c] = 0.f;
}

__global__ __launch_bounds__(256) void stats_k(const float* __restrict__ z, int n) {
    __shared__ float red1[8][128];
    __shared__ float red2[8][128];
    int tid = threadIdx.x, w = tid >> 5, l = tid & 31;
    float4 s = make_float4(0.f, 0.f, 0.f, 0.f);
    float4 q = make_float4(0.f, 0.f, 0.f, 0.f);
    for (int r = blockIdx.x * 8 + w; r < n; r += gridDim.x * 8) {
        float4 v = ((const float4*)z)[(size_t)r * 32 + l];
        s.x += v.x; s.y += v.y; s.z += v.z; s.w += v.w;
        q.x += v.x * v.x; q.y += v.y * v.y; q.z += v.z * v.z; q.w += v.w * v.w;
    }
    ((float4*)&red1[w][0])[l] = s;
    ((float4*)&red2[w][0])[l] = q;
    __syncthreads();
    if (tid < 128) {
        float a = 0.f, b = 0.f;
        #pragma unroll
        for (int t = 0; t < 8; t++) { a += red1[t][tid]; b += red2[t][tid]; }
        atomicAdd(&g_sum[tid], a);
        atomicAdd(&g_sumsq[tid], b);
    }
}

__global__ void finalize_k(const float* __restrict__ nw, const float* __restrict__ nb,
                           const float* __restrict__ na, float inv_n)
{
    int c = threadIdx.x;
    float s = g_sum[c], q = g_sumsq[c];
    g_sum[c] = 0.f;
    g_sumsq[c] = 0.f;
    float mu  = s * inv_n;
    float ez2 = q * inv_n;
    float a = na[c];
    float var = ez2 - (2.f * a - a * a) * mu * mu;
    float inv = rsqrtf(var + 1e-5f);
    g_scale[c] = nw[c] * inv;
    g_shift[c] = nb[c] - nw[c] * inv * a * mu;
}

__global__ __launch_bounds__(256) void decode_k(
    const float* __restrict__ z, const float* __restrict__ dec_w,
    const float* __restrict__ dec_b, float* __restrict__ out, int n)
{
    int lane = threadIdx.x & 31;
    int node = blockIdx.x * 8 + (threadIdx.x >> 5);
    if (node >= n) return;
    float4 sc = ((const float4*)g_scale)[lane];
    float4 sh = ((const float4*)g_shift)[lane];
    float4 zv = ((const float4*)z)[node * 32 + lane];
    float4 hv;
    hv.x = fmaxf(fmaf(zv.x, sc.x, sh.x), 0.f);
    hv.y = fmaxf(fmaf(zv.y, sc.y, sh.y), 0.f);
    hv.z = fmaxf(fmaf(zv.z, sc.z, sh.z), 0.f);
    hv.w = fmaxf(fmaf(zv.w, sc.w, sh.w), 0.f);
    float4 dw = ((const float4*)dec_w)[lane];
    float p = hv.x * dw.x + hv.y * dw.y + hv.z * dw.z + hv.w * dw.w;
    #pragma unroll
    for (int o = 16; o > 0; o >>= 1) p += __shfl_down_sync(0xffffffffu, p, o);
    if (lane == 0) out[node] = p + dec_b[0];
}

// ---------------- launch ------------------------------------------------------
extern "C" void kernel_launch(void* const* d_in, const int* in_sizes, int n_in,
                              void* d_out, int out_size)
{
    const float* x      = (const float*)d_in[0];
    const int*   ei     = (const int*)d_in[1];
    const float* ea     = (const float*)d_in[2];
    const float* enc_w1 = (const float*)d_in[3];
    const float* enc_b1 = (const float*)d_in[4];
    const float* enc_w2 = (const float*)d_in[5];
    const float* enc_b2 = (const float*)d_in[6];
    const float* edge_w = (const float*)d_in[7];
    const float* edge_b = (const float*)d_in[8];
    const float* mlp_w1 = (const float*)d_in[9];
    const float* mlp_b1 = (const float*)d_in[10];
    const float* mlp_w2 = (const float*)d_in[11];
    const float* mlp_b2 = (const float*)d_in[12];
    const float* norm_w = (const float*)d_in[13];
    const float* norm_b = (const float*)d_in[14];
    const float* norm_a = (const float*)d_in[15];
    const float* dec_w  = (const float*)d_in[16];
    const float* dec_b  = (const float*)d_in[17];

    int n = in_sizes[0] / 64;
    int e = in_sizes[2] / 8;
    const int* src = ei;
    const int* dst = ei + e;

    float *g_h_p, *g_tmp_p, *g_agg_p;
    char* wbuf;
    cudaGetSymbolAddress((void**)&g_h_p, g_h);
    cudaGetSymbolAddress((void**)&g_tmp_p, g_tmp);
    cudaGetSymbolAddress((void**)&g_agg_p, g_agg);
    cudaGetSymbolAddress((void**)&wbuf, g_wbuf);

    const uint4* w_enc1 = (const uint4*)(wbuf + 0);
    const uint4* w_enc2 = (const uint4*)(wbuf + 32768);

    const int SMEM = 98304;
    cudaFuncSetAttribute(fused_mlp_k<64>,  cudaFuncAttributeMaxDynamicSharedMemorySize, SMEM);
    cudaFuncSetAttribute(fused_mlp_k<128>, cudaFuncAttributeMaxDynamicSharedMemorySize, SMEM);

    int gb_nodes = (n + 255) / 256;
    int gb_edges = (e + 255) / 256;
    int gb_gemm  = (n + 127) / 128;
    int gb_warp8 = (n + 7) / 8;

    // ---- launch order keeps the encoder fused MLP 4th for ncu ----
    zero_cnt_k<<<gb_nodes, 256>>>(n);                    // 1
    hist_k<<<gb_edges, 256>>>(dst, e);                   // 2
    wprep_k<<<76, 256>>>(enc_w1, enc_w2, mlp_w1, mlp_w2);// 3
    fused_mlp_k<64><<<gb_gemm, 512, SMEM>>>(             // 4  <- profiled
        x, w_enc1, enc_b1, w_enc2, enc_b2, g_h_p, n);
    zero_stats_k<<<1, 128>>>();                          // 5
    scan1_k<<<gb_nodes, 256>>>(n);                       // 6
    scan2_k<<<1, 256>>>(gb_nodes);                       // 7
    scan3_k<<<gb_nodes, 256>>>(n);                       // 8 (also zeroes g_cnt)
    fill_k<<<gb_edges, 256>>>(src, dst, e);              // 9

    // ---- layers (z ping-pong: g_h -> g_tmp -> g_h -> ...) ----
    float* zin  = g_h_p;
    float* zout = g_tmp_p;
    for (int l = 0; l < 4; l++) {
        const uint4* w1s = (const uint4*)(wbuf + 98304 + l * 65536);
        const uint4* w2s = (const uint4*)(wbuf + 360448 + l * 65536);
        // agg output = h_node + sum(msg) -> single-input MLP
        if (l == 0) {
            agg_k<false><<<gb_warp8, 256>>>(zin, edge_w + l * 8 * 128, edge_b + l * 128, ea, g_agg_p, n);
        } else {
            agg_k<true><<<gb_warp8, 256>>>(zin, edge_w + l * 8 * 128, edge_b + l * 128, ea, g_agg_p, n);
        }
        fused_mlp_k<128><<<gb_gemm, 512, SMEM>>>(
            g_agg_p, w1s, mlp_b1 + l * 128, w2s, mlp_b2 + l * 128, zout, n);
        stats_k<<<256, 256>>>(zout, n);
        finalize_k<<<1, 128>>>(norm_w + l * 128, norm_b + l * 128, norm_a + l * 128,
                               1.f / (float)n);
        float* t = zin; zin = zout; zout = t;
    }
    // zin now holds z of layer 3
    decode_k<<<gb_warp8, 256>>>(zin, dec_w, dec_b, (float*)d_out, n);
}

// round 16
// speedup vs baseline: 1.2352x; 1.0366x over previous
#include <cuda_runtime.h>
#include <cuda_bf16.h>
#include <cstdint>

#define NMAX 50000
#define EMAX 600000
#define H 128

// ---------------- scratch (device globals; no allocation allowed) -------------
__device__ float g_h[NMAX * H];
__device__ float g_tmp[NMAX * H];
__device__ float g_agg[NMAX * H];
__device__ int   g_rptr[NMAX + 1];
__device__ int   g_cnt[NMAX];
__device__ int   g_part[256];
__device__ int   g_perm[NMAX];
__device__ int   g_dhist[256];
__device__ int   g_dcur[256];
__device__ int2  g_csr[EMAX];
__device__ float g_sum[H];
__device__ float g_sumsq[H];
__device__ float g_scale[H];
__device__ float g_shift[H];
// pre-split weights: hi/lo bf16 planes in final swizzled layout
__device__ __align__(16) char g_wbuf[622592];

// ---------------- helpers -----------------------------------------------------
__device__ __forceinline__ uint32_t smem_to_u32(const void* p) {
    uint32_t a;
    asm("{ .reg .u64 t; cvta.to.shared.u64 t, %1; cvt.u32.u64 %0, t; }" : "=r"(a) : "l"(p));
    return a;
}

#define LDSM4(r0, r1, r2, r3, addr) \
    asm volatile("ldmatrix.sync.aligned.m8n8.x4.shared.b16 {%0,%1,%2,%3}, [%4];" \
        : "=r"(r0), "=r"(r1), "=r"(r2), "=r"(r3) : "r"(addr))

#define MMA16816(d, a, b0v, b1v) \
    asm volatile("mma.sync.aligned.m16n8k16.row.col.f32.bf16.bf16.f32 " \
        "{%0,%1,%2,%3},{%4,%5,%6,%7},{%8,%9},{%0,%1,%2,%3};" \
        : "+f"((d)[0]), "+f"((d)[1]), "+f"((d)[2]), "+f"((d)[3]) \
        : "r"((a)[0]), "r"((a)[1]), "r"((a)[2]), "r"((a)[3]), "r"(b0v), "r"(b1v))

__device__ __forceinline__ void cvt_pair(float a, float b, uint32_t& hi, uint32_t& lo) {
    __nv_bfloat16 ha = __float2bfloat16(a), hb = __float2bfloat16(b);
    __nv_bfloat16 la = __float2bfloat16(a - __bfloat162float(ha));
    __nv_bfloat16 lb = __float2bfloat16(b - __bfloat162float(hb));
    __nv_bfloat162 hp; hp.x = ha; hp.y = hb;
    __nv_bfloat162 lp; lp.x = la; lp.y = lb;
    hi = *reinterpret_cast<uint32_t*>(&hp);
    lo = *reinterpret_cast<uint32_t*>(&lp);
}

// 3-pass split MMA over one 64-K chunk; warp tile 32x32 (mi 2 x ni 4) [R9 form]
__device__ __forceinline__ void mma3pass(uint32_t sb, uint32_t aH, uint32_t aL,
                                         uint32_t bH, uint32_t bL,
                                         int rmb, int n0w, int lid,
                                         float acc[2][4][4])
{
    #pragma unroll
    for (int pass = 0; pass < 3; pass++) {
        uint32_t aoff = (pass == 2) ? aL : aH;
        uint32_t boff = (pass == 1) ? bL : bH;
        #pragma unroll
        for (int ks = 0; ks < 4; ks++) {
            int crow = ks * 2 + (lid >> 4);
            uint32_t af[2][4], bf[2][4];
            #pragma unroll
            for (int mi = 0; mi < 2; mi++) {
                int row = rmb + mi * 16 + (lid & 15);
                uint32_t ad = sb + aoff + row * 128 + ((crow ^ (row & 7)) << 4);
                LDSM4(af[mi][0], af[mi][1], af[mi][2], af[mi][3], ad);
            }
            #pragma unroll
            for (int bi = 0; bi < 2; bi++) {
                int rn = n0w + bi * 16 + (lid & 15);
                uint32_t bd = sb + boff + rn * 128 + ((crow ^ (rn & 7)) << 4);
                LDSM4(bf[bi][0], bf[bi][1], bf[bi][2], bf[bi][3], bd);
            }
            #pragma unroll
            for (int mi = 0; mi < 2; mi++)
                #pragma unroll
                for (int ni = 0; ni < 4; ni++) {
                    uint32_t b0v = bf[ni >> 1][ni & 1];
                    uint32_t b1v = bf[ni >> 1][(ni & 1) + 2];
                    MMA16816(acc[mi][ni], af[mi], b0v, b1v);
                }
        }
    }
}

// ---------------- weight pre-split kernel -------------------------------------
__global__ __launch_bounds__(256) void wprep_k(
    const float* __restrict__ enc_w1, const float* __restrict__ enc_w2,
    const float* __restrict__ mlp_w1, const float* __restrict__ mlp_w2)
{
    int g = blockIdx.x * 256 + threadIdx.x;
    const float* W;
    uint32_t bufoff;
    int local;
    if (g < 1024)       { W = enc_w1; bufoff = 0;     local = g; }
    else if (g < 3072)  { W = enc_w2; bufoff = 32768; local = g - 1024; }
    else if (g < 11264) {
        int l = (g - 3072) >> 11;
        W = mlp_w1 + l * 16384; bufoff = 98304 + l * 65536; local = (g - 3072) & 2047;
    } else if (g < 19456) {
        int l = (g - 11264) >> 11;
        W = mlp_w2 + l * 16384; bufoff = 360448 + l * 65536; local = (g - 11264) & 2047;
    } else return;

    int nn = local & 127;
    int t  = local >> 7;
    int ci = t >> 3, cc = t & 7;
    float v[8];
    #pragma unroll
    for (int j = 0; j < 8; j++)
        v[j] = W[(size_t)(ci * 64 + cc * 8 + j) * 128 + nn];
    uint4 hi, lo;
    cvt_pair(v[0], v[1], hi.x, lo.x);
    cvt_pair(v[2], v[3], hi.y, lo.y);
    cvt_pair(v[4], v[5], hi.z, lo.z);
    cvt_pair(v[6], v[7], hi.w, lo.w);
    uint32_t off = nn * 128 + ((cc ^ (nn & 7)) << 4);
    char* base = g_wbuf + bufoff + ci * 32768;
    *(uint4*)(base + off) = hi;
    *(uint4*)(base + 16384 + off) = lo;
}

// ---------------- block-scan helper (256 threads, inclusive) ------------------
__device__ __forceinline__ int block_scan_256(int v, int tid, int* wsum) {
    int lane = tid & 31, wid = tid >> 5;
    #pragma unroll
    for (int o = 1; o < 32; o <<= 1) {
        int t = __shfl_up_sync(0xffffffffu, v, o);
        if (lane >= o) v += t;
    }
    if (lane == 31) wsum[wid] = v;
    __syncthreads();
    if (wid == 0) {
        int s = (lane < 8) ? wsum[lane] : 0;
        #pragma unroll
        for (int o = 1; o < 8; o <<= 1) {
            int t = __shfl_up_sync(0xffffffffu, s, o);
            if (lane >= o) s += t;
        }
        if (lane < 8) wsum[lane] = s;
    }
    __syncthreads();
    if (wid > 0) v += wsum[wid - 1];
    return v;
}

// ---------------- CSR build ---------------------------------------------------
__global__ void zero_cnt_k(int n) {
    int i = blockIdx.x * blockDim.x + threadIdx.x;
    if (i < n) g_cnt[i] = 0;
    if (blockIdx.x == 0 && threadIdx.x < 256) {
        g_dhist[threadIdx.x] = 0;
        g_dcur[threadIdx.x] = 0;
    }
}
__global__ void hist_k(const int* __restrict__ dst, int e) {
    int i = blockIdx.x * blockDim.x + threadIdx.x;
    if (i < e) atomicAdd(&g_cnt[dst[i]], 1);
}
// degree histogram for counting sort (bin = 255 - min(deg,255): descending)
__global__ void dhist_k(int n) {
    int i = blockIdx.x * blockDim.x + threadIdx.x;
    if (i < n) {
        int b = 255 - min(g_cnt[i], 255);
        atomicAdd(&g_dhist[b], 1);
    }
}
// exclusive scan of 256 degree bins (1 block)
__global__ __launch_bounds__(256) void dscan_k() {
    __shared__ int wsum[32];
    int tid = threadIdx.x;
    int v = g_dhist[tid];
    int inc = block_scan_256(v, tid, wsum);
    g_dhist[tid] = inc - v;
}
// scatter nodes into degree-sorted permutation
__global__ void dscatter_k(int n) {
    int i = blockIdx.x * blockDim.x + threadIdx.x;
    if (i < n) {
        int b = 255 - min(g_cnt[i], 255);
        int pos = g_dhist[b] + atomicAdd(&g_dcur[b], 1);
        g_perm[pos] = i;
    }
}
__global__ __launch_bounds__(256) void scan1_k(int n) {
    __shared__ int wsum[32];
    int tid = threadIdx.x, lane = tid & 31, wid = tid >> 5;
    int i = blockIdx.x * 256 + tid;
    int v = (i < n) ? g_cnt[i] : 0;
    #pragma unroll
    for (int o = 16; o > 0; o >>= 1) v += __shfl_down_sync(0xffffffffu, v, o);
    if (lane == 0) wsum[wid] = v;
    __syncthreads();
    if (wid == 0) {
        int s = (lane < 8) ? wsum[lane] : 0;
        #pragma unroll
        for (int o = 4; o > 0; o >>= 1) s += __shfl_down_sync(0xffffffffu, s, o);
        if (lane == 0) g_part[blockIdx.x] = s;
    }
}
__global__ __launch_bounds__(256) void scan2_k(int nb) {
    __shared__ int wsum[32];
    int tid = threadIdx.x;
    int v = (tid < nb) ? g_part[tid] : 0;
    int inc = block_scan_256(v, tid, wsum);
    if (tid < nb) g_part[tid] = inc - v;
}
// scan3 also re-zeros g_cnt for fill_k (saves a separate zero pass)
__global__ __launch_bounds__(256) void scan3_k(int n) {
    __shared__ int wsum[32];
    int tid = threadIdx.x;
    int i = blockIdx.x * 256 + tid;
    int v = (i < n) ? g_cnt[i] : 0;
    int inc = block_scan_256(v, tid, wsum);
    if (i < n) {
        g_rptr[i + 1] = inc + g_part[blockIdx.x];
        g_cnt[i] = 0;
    }
    if (i == 0) g_rptr[0] = 0;
}
__global__ void fill_k(const int* __restrict__ src, const int* __restrict__ dst, int e) {
    int i = blockIdx.x * blockDim.x + threadIdx.x;
    if (i < e) {
        int d = dst[i];
        int p = g_rptr[d] + atomicAdd(&g_cnt[d], 1);
        g_csr[p] = make_int2(src[i], i);
    }
}

// ---------------- fused 2-layer MLP (512 threads, 32x32 warp tiles) -----------
// A comes pre-combined (agg output already includes the normalized self term),
// so staging is a single straight read + split.
template<int KA>
__global__ __launch_bounds__(512) void fused_mlp_k(
    const float* __restrict__ Z,
    const uint4* __restrict__ w1s, const float* __restrict__ b1,
    const uint4* __restrict__ w2s, const float* __restrict__ b2,
    float* __restrict__ C, int M)
{
    extern __shared__ __align__(128) char smem[];
    uint32_t sb = smem_to_u32(smem);
    const uint32_t AH = 0, AL = 16384, BH = 32768;
    const uint32_t C1H = 0, C1L = 32768, B2H = 65536;

    int tid = threadIdx.x, lid = tid & 31, wid = tid >> 5;
    int m0 = blockIdx.x * 128;
    int rmb = (wid & 3) * 32;
    int n0w = (wid >> 2) * 32;
    int qr = lid >> 2, qc = lid & 3;

    float acc[2][4][4];
    #pragma unroll
    for (int mi = 0; mi < 2; mi++)
        #pragma unroll
        for (int ni = 0; ni < 4; ni++)
            #pragma unroll
            for (int j = 0; j < 4; j++) acc[mi][ni][j] = 0.f;

    // ================= GEMM 1 =================
    for (int kc = 0; kc < KA; kc += 64) {
        if (kc) __syncthreads();
        #pragma unroll
        for (int i = 0; i < 2; i++) {
            int cid = tid + i * 512;
            int r = cid >> 3, c = cid & 7;
            int gr = m0 + r;
            int col0 = kc + c * 8;
            float v[8];
            if (gr < M) {
                const float4* p = (const float4*)(Z + (size_t)gr * KA + col0);
                float4 v0 = p[0], v1 = p[1];
                v[0] = v0.x; v[1] = v0.y; v[2] = v0.z; v[3] = v0.w;
                v[4] = v1.x; v[5] = v1.y; v[6] = v1.z; v[7] = v1.w;
            } else {
                #pragma unroll
                for (int j = 0; j < 8; j++) v[j] = 0.f;
            }
            uint4 hi, lo;
            cvt_pair(v[0], v[1], hi.x, lo.x);
            cvt_pair(v[2], v[3], hi.y, lo.y);
            cvt_pair(v[4], v[5], hi.z, lo.z);
            cvt_pair(v[6], v[7], hi.w, lo.w);
            uint32_t off = r * 128 + ((c ^ (r & 7)) << 4);
            *(uint4*)(smem + AH + off) = hi;
            *(uint4*)(smem + AL + off) = lo;
        }
        {
            const uint4* wp = w1s + (kc >> 6) * 2048;
            #pragma unroll
            for (int i = 0; i < 4; i++) {
                int idx = tid + i * 512;
                ((uint4*)(smem + BH))[idx] = wp[idx];
            }
        }
        __syncthreads();
        mma3pass(sb, AH, AL, BH, BH + 16384, rmb, n0w, lid, acc);
    }
    __syncthreads();

    // ================= C1 = relu(acc + b1) -> smem bf16 split =================
    #pragma unroll
    for (int ni = 0; ni < 4; ni++) {
        int col = n0w + ni * 8 + qc * 2;
        float bb0 = __ldg(b1 + col), bb1 = __ldg(b1 + col + 1);
        uint32_t plane = (uint32_t)(col >> 6) * 16384u;
        int cl = col & 63;
        int cc = cl >> 3;
        uint32_t cb = (uint32_t)((cl & 7) * 2);
        #pragma unroll
        for (int mi = 0; mi < 2; mi++) {
            int r0 = rmb + mi * 16 + qr;
            int r1 = r0 + 8;
            float o00 = fmaxf(acc[mi][ni][0] + bb0, 0.f);
            float o01 = fmaxf(acc[mi][ni][1] + bb1, 0.f);
            float o10 = fmaxf(acc[mi][ni][2] + bb0, 0.f);
            float o11 = fmaxf(acc[mi][ni][3] + bb1, 0.f);
            uint32_t h0, l0, h1, l1;
            cvt_pair(o00, o01, h0, l0);
            cvt_pair(o10, o11, h1, l1);
            uint32_t off0 = plane + r0 * 128 + ((cc ^ (r0 & 7)) << 4) + cb;
            uint32_t off1 = plane + r1 * 128 + ((cc ^ (r1 & 7)) << 4) + cb;
            *(uint32_t*)(smem + C1H + off0) = h0;
            *(uint32_t*)(smem + C1L + off0) = l0;
            *(uint32_t*)(smem + C1H + off1) = h1;
            *(uint32_t*)(smem + C1L + off1) = l1;
        }
    }
    #pragma unroll
    for (int mi = 0; mi < 2; mi++)
        #pragma unroll
        for (int ni = 0; ni < 4; ni++)
            #pragma unroll
            for (int j = 0; j < 4; j++) acc[mi][ni][j] = 0.f;

    // ================= GEMM 2 (K = 128, A = C1 in smem) =================
    for (int kc = 0; kc < 128; kc += 64) {
        if (kc) __syncthreads();
        {
            const uint4* wp = w2s + (kc >> 6) * 2048;
            #pragma unroll
            for (int i = 0; i < 4; i++) {
                int idx = tid + i * 512;
                ((uint4*)(smem + B2H))[idx] = wp[idx];
            }
        }
        __syncthreads();
        uint32_t plane = (uint32_t)(kc >> 6) * 16384u;
        mma3pass(sb, C1H + plane, C1L + plane, B2H, B2H + 16384, rmb, n0w, lid, acc);
    }

    // ================= epilogue: z = acc + b2 (no relu) =================
    #pragma unroll
    for (int ni = 0; ni < 4; ni++) {
        int col = n0w + ni * 8 + qc * 2;
        float b0 = __ldg(b2 + col), b1v = __ldg(b2 + col + 1);
        #pragma unroll
        for (int mi = 0; mi < 2; mi++) {
            int gr = m0 + rmb + mi * 16 + qr;
            float2 o0 = make_float2(acc[mi][ni][0] + b0, acc[mi][ni][1] + b1v);
            float2 o1 = make_float2(acc[mi][ni][2] + b0, acc[mi][ni][3] + b1v);
            if (gr < M)     *(float2*)(C + (size_t)gr * 128 + col) = o0;
            if (gr + 8 < M) *(float2*)(C + (size_t)(gr + 8) * 128 + col) = o1;
        }
    }
}

// ---------------- GINE aggregate (warp per node via degree-sorted perm) -------
// Output = h_node + sum_edges relu(h_src + lin(ea)), h = NORM ? relu(z*sc+sh) : z.
// Nodes processed in descending-degree order: warps in a block get near-equal
// work, blocks retire together, big nodes start first (tail hiding).
template<bool NORM>
__global__ __launch_bounds__(256) void agg_k(
    const float* __restrict__ h, const float* __restrict__ We,
    const float* __restrict__ be, const float* __restrict__ ea,
    float* __restrict__ out, int n)
{
    int lane = threadIdx.x & 31;
    int gid = blockIdx.x * 8 + (threadIdx.x >> 5);

    const float4* We4 = (const float4*)We;
    float4 w[8];
    #pragma unroll
    for (int k = 0; k < 8; k++) w[k] = We4[k * 32 + lane];
    float4 bev = ((const float4*)be)[lane];
    float4 sc, sh;
    if (NORM) {
        sc = ((const float4*)g_scale)[lane];
        sh = ((const float4*)g_shift)[lane];
    }

    if (gid >= n) return;
    int node = g_perm[gid];
    int s = g_rptr[node], e = g_rptr[node + 1];

    const float4* h4  = (const float4*)h;
    const float4* ea4 = (const float4*)ea;

    // self term: h_node (normalized) — z_i = h_i + agg_i
    float4 acc = h4[node * 32 + lane];
    if (NORM) {
        acc.x = fmaxf(fmaf(acc.x, sc.x, sh.x), 0.f);
        acc.y = fmaxf(fmaf(acc.y, sc.y, sh.y), 0.f);
        acc.z = fmaxf(fmaf(acc.z, sc.z, sh.z), 0.f);
        acc.w = fmaxf(fmaf(acc.w, sc.w, sh.w), 0.f);
    }

    for (int i = s; i < e; i++) {
        int2 se = g_csr[i];
        float4 a0 = ea4[se.y * 2];
        float4 a1 = ea4[se.y * 2 + 1];
        float4 hv = h4[se.x * 32 + lane];
        if (NORM) {
            hv.x = fmaxf(fmaf(hv.x, sc.x, sh.x), 0.f);
            hv.y = fmaxf(fmaf(hv.y, sc.y, sh.y), 0.f);
            hv.z = fmaxf(fmaf(hv.z, sc.z, sh.z), 0.f);
            hv.w = fmaxf(fmaf(hv.w, sc.w, sh.w), 0.f);
        }
        float4 lin = bev;
        #define ACCW(comp, wi) \
            lin.x = fmaf(comp, w[wi].x, lin.x); lin.y = fmaf(comp, w[wi].y, lin.y); \
            lin.z = fmaf(comp, w[wi].z, lin.z); lin.w = fmaf(comp, w[wi].w, lin.w);
        ACCW(a0.x, 0) ACCW(a0.y, 1) ACCW(a0.z, 2) ACCW(a0.w, 3)
        ACCW(a1.x, 4) ACCW(a1.y, 5) ACCW(a1.z, 6) ACCW(a1.w, 7)
        #undef ACCW
        acc.x += fmaxf(hv.x + lin.x, 0.f);
        acc.y += fmaxf(hv.y + lin.y, 0.f);
        acc.z += fmaxf(hv.z + lin.z, 0.f);
        acc.w += fmaxf(hv.w + lin.w, 0.f);
    }
    ((float4*)out)[node * 32 + lane] = acc;
}

// ---------------- GraphNorm ---------------------------------------------------
__global__ void zero_stats_k() {
    int c = threadIdx.x;
    g_sum[c] = 0.f;
    g_sumsq[c] = 0.f;
}

__global__ __launch_bounds__(256) void stats_k(const float* __restrict__ z, int n) {
    __shared__ float red1[8][128];
    __shared__ float red2[8][128];
    int tid = threadIdx.x, w = tid >> 5, l = tid & 31;
    float4 s = make_float4(0.f, 0.f, 0.f, 0.f);
    float4 q = make_float4(0.f, 0.f, 0.f, 0.f);
    for (int r = blockIdx.x * 8 + w; r < n; r += gridDim.x * 8) {
        float4 v = ((const float4*)z)[(size_t)r * 32 + l];
        s.x += v.x; s.y += v.y; s.z += v.z; s.w += v.w;
        q.x += v.x * v.x; q.y += v.y * v.y; q.z += v.z * v.z; q.w += v.w * v.w;
    }
    ((float4*)&red1[w][0])[l] = s;
    ((float4*)&red2[w][0])[l] = q;
    __syncthreads();
    if (tid < 128) {
        float a = 0.f, b = 0.f;
        #pragma unroll
        for (int t = 0; t < 8; t++) { a += red1[t][tid]; b += red2[t][tid]; }
        atomicAdd(&g_sum[tid], a);
        atomicAdd(&g_sumsq[tid], b);
    }
}

__global__ void finalize_k(const float* __restrict__ nw, const float* __restrict__ nb,
                           const float* __restrict__ na, float inv_n)
{
    int c = threadIdx.x;
    float s = g_sum[c], q = g_sumsq[c];
    g_sum[c] = 0.f;
    g_sumsq[c] = 0.f;
    float mu  = s * inv_n;
    float ez2 = q * inv_n;
    float a = na[c];
    float var = ez2 - (2.f * a - a * a) * mu * mu;
    float inv = rsqrtf(var + 1e-5f);
    g_scale[c] = nw[c] * inv;
    g_shift[c] = nb[c] - nw[c] * inv * a * mu;
}

__global__ __launch_bounds__(256) void decode_k(
    const float* __restrict__ z, const float* __restrict__ dec_w,
    const float* __restrict__ dec_b, float* __restrict__ out, int n)
{
    int lane = threadIdx.x & 31;
    int node = blockIdx.x * 8 + (threadIdx.x >> 5);
    if (node >= n) return;
    float4 sc = ((const float4*)g_scale)[lane];
    float4 sh = ((const float4*)g_shift)[lane];
    float4 zv = ((const float4*)z)[node * 32 + lane];
    float4 hv;
    hv.x = fmaxf(fmaf(zv.x, sc.x, sh.x), 0.f);
    hv.y = fmaxf(fmaf(zv.y, sc.y, sh.y), 0.f);
    hv.z = fmaxf(fmaf(zv.z, sc.z, sh.z), 0.f);
    hv.w = fmaxf(fmaf(zv.w, sc.w, sh.w), 0.f);
    float4 dw = ((const float4*)dec_w)[lane];
    float p = hv.x * dw.x + hv.y * dw.y + hv.z * dw.z + hv.w * dw.w;
    #pragma unroll
    for (int o = 16; o > 0; o >>= 1) p += __shfl_down_sync(0xffffffffu, p, o);
    if (lane == 0) out[node] = p + dec_b[0];
}

// ---------------- launch ------------------------------------------------------
extern "C" void kernel_launch(void* const* d_in, const int* in_sizes, int n_in,
                              void* d_out, int out_size)
{
    const float* x      = (const float*)d_in[0];
    const int*   ei     = (const int*)d_in[1];
    const float* ea     = (const float*)d_in[2];
    const float* enc_w1 = (const float*)d_in[3];
    const float* enc_b1 = (const float*)d_in[4];
    const float* enc_w2 = (const float*)d_in[5];
    const float* enc_b2 = (const float*)d_in[6];
    const float* edge_w = (const float*)d_in[7];
    const float* edge_b = (const float*)d_in[8];
    const float* mlp_w1 = (const float*)d_in[9];
    const float* mlp_b1 = (const float*)d_in[10];
    const float* mlp_w2 = (const float*)d_in[11];
    const float* mlp_b2 = (const float*)d_in[12];
    const float* norm_w = (const float*)d_in[13];
    const float* norm_b = (const float*)d_in[14];
    const float* norm_a = (const float*)d_in[15];
    const float* dec_w  = (const float*)d_in[16];
    const float* dec_b  = (const float*)d_in[17];

    int n = in_sizes[0] / 64;
    int e = in_sizes[2] / 8;
    const int* src = ei;
    const int* dst = ei + e;

    float *g_h_p, *g_tmp_p, *g_agg_p;
    char* wbuf;
    cudaGetSymbolAddress((void**)&g_h_p, g_h);
    cudaGetSymbolAddress((void**)&g_tmp_p, g_tmp);
    cudaGetSymbolAddress((void**)&g_agg_p, g_agg);
    cudaGetSymbolAddress((void**)&wbuf, g_wbuf);

    const uint4* w_enc1 = (const uint4*)(wbuf + 0);
    const uint4* w_enc2 = (const uint4*)(wbuf + 32768);

    const int SMEM = 98304;
    cudaFuncSetAttribute(fused_mlp_k<64>,  cudaFuncAttributeMaxDynamicSharedMemorySize, SMEM);
    cudaFuncSetAttribute(fused_mlp_k<128>, cudaFuncAttributeMaxDynamicSharedMemorySize, SMEM);

    int gb_nodes = (n + 255) / 256;
    int gb_edges = (e + 255) / 256;
    int gb_gemm  = (n + 127) / 128;
    int gb_warp8 = (n + 7) / 8;

    // ---- launch order keeps the encoder fused MLP 4th for ncu ----
    zero_cnt_k<<<gb_nodes, 256>>>(n);                    // 1 (also zeroes dhist/dcur)
    hist_k<<<gb_edges, 256>>>(dst, e);                   // 2
    wprep_k<<<76, 256>>>(enc_w1, enc_w2, mlp_w1, mlp_w2);// 3
    fused_mlp_k<64><<<gb_gemm, 512, SMEM>>>(             // 4  <- profiled
        x, w_enc1, enc_b1, w_enc2, enc_b2, g_h_p, n);
    zero_stats_k<<<1, 128>>>();                          // 5
    dhist_k<<<gb_nodes, 256>>>(n);                       // 6
    dscan_k<<<1, 256>>>();                               // 7
    dscatter_k<<<gb_nodes, 256>>>(n);                    // 8
    scan1_k<<<gb_nodes, 256>>>(n);                       // 9
    scan2_k<<<1, 256>>>(gb_nodes);                       // 10
    scan3_k<<<gb_nodes, 256>>>(n);                       // 11 (also zeroes g_cnt)
    fill_k<<<gb_edges, 256>>>(src, dst, e);              // 12

    // ---- layers (z ping-pong: g_h -> g_tmp -> g_h -> ...) ----
    float* zin  = g_h_p;
    float* zout = g_tmp_p;
    for (int l = 0; l < 4; l++) {
        const uint4* w1s = (const uint4*)(wbuf + 98304 + l * 65536);
        const uint4* w2s = (const uint4*)(wbuf + 360448 + l * 65536);
        // agg output = h_node + sum(msg) -> single-input MLP
        if (l == 0) {
            agg_k<false><<<gb_warp8, 256>>>(zin, edge_w + l * 8 * 128, edge_b + l * 128, ea, g_agg_p, n);
        } else {
            agg_k<true><<<gb_warp8, 256>>>(zin, edge_w + l * 8 * 128, edge_b + l * 128, ea, g_agg_p, n);
        }
        fused_mlp_k<128><<<gb_gemm, 512, SMEM>>>(
            g_agg_p, w1s, mlp_b1 + l * 128, w2s, mlp_b2 + l * 128, zout, n);
        stats_k<<<256, 256>>>(zout, n);
        finalize_k<<<1, 128>>>(norm_w + l * 128, norm_b + l * 128, norm_a + l * 128,
                               1.f / (float)n);
        float* t = zin; zin = zout; zout = t;
    }
    // zin now holds z of layer 3
    decode_k<<<gb_warp8, 256>>>(zin, dec_w, dec_b, (float*)d_out, n);
}